// round 12
// baseline (speedup 1.0000x reference)
#include <cuda_runtime.h>
#include <cuda_fp16.h>
#include <math.h>
#include <stdint.h>

// Problem constants
#define TT 4096   // tokens = B*S
#define EE 64     // experts
#define KK 8      // top_k
#define HH 1024   // hidden
#define FF 512    // expert ffn
#define CC 1024   // capacity

// -------- scratch (__device__ globals; no allocation allowed) --------
__device__ int   g_expert_index[TT * KK];
__device__ float g_weights[TT * KK];
__device__ int   g_pair_pos[TT * KK];
__device__ int   g_row_token[EE * CC];
__device__ int   g_count[EE];
__device__ alignas(16) __half g_xh[(size_t)TT * HH];          // 8 MB
__device__ alignas(16) __half g_wgh[(size_t)EE * HH * FF];    // 67 MB
__device__ alignas(16) __half g_wuh[(size_t)EE * HH * FF];    // 67 MB
__device__ alignas(16) __half g_wdh[(size_t)EE * FF * HH];    // 67 MB
__device__ alignas(16) __half g_hbuf[(size_t)EE * CC * FF];   // 67 MB
__device__ alignas(16) __half g_obuf[(size_t)EE * CC * HH];   // 134 MB

// -------- helpers --------
__device__ __forceinline__ uint32_t smem_to_u32(const void* p) {
    uint32_t a;
    asm("{ .reg .u64 t; cvta.to.shared.u64 t, %1; cvt.u32.u64 %0, t; }"
        : "=r"(a) : "l"(p));
    return a;
}
__device__ __forceinline__ uint2 f4_to_h4(float4 v) {
    __half2 a = __floats2half2_rn(v.x, v.y);
    __half2 b = __floats2half2_rn(v.z, v.w);
    uint2 r;
    r.x = *reinterpret_cast<uint32_t*>(&a);
    r.y = *reinterpret_cast<uint32_t*>(&b);
    return r;
}
__device__ __forceinline__ uint4 f8_to_h8(float4 v0, float4 v1) {
    uint2 a = f4_to_h4(v0);
    uint2 b = f4_to_h4(v1);
    return make_uint4(a.x, a.y, b.x, b.y);
}
__device__ __forceinline__ void ldm_x4(uint32_t* r, uint32_t addr) {
    asm volatile("ldmatrix.sync.aligned.m8n8.x4.shared.b16 {%0,%1,%2,%3}, [%4];"
        : "=r"(r[0]), "=r"(r[1]), "=r"(r[2]), "=r"(r[3]) : "r"(addr));
}
__device__ __forceinline__ void ldm_x4t(uint32_t* r, uint32_t addr) {
    asm volatile("ldmatrix.sync.aligned.m8n8.x4.trans.shared.b16 {%0,%1,%2,%3}, [%4];"
        : "=r"(r[0]), "=r"(r[1]), "=r"(r[2]), "=r"(r[3]) : "r"(addr));
}
__device__ __forceinline__ void mma_f16(float* c, const uint32_t* a, const uint32_t* b) {
    asm volatile(
        "mma.sync.aligned.m16n8k16.row.col.f32.f16.f16.f32 "
        "{%0,%1,%2,%3},{%4,%5,%6,%7},{%8,%9},{%0,%1,%2,%3};"
        : "+f"(c[0]), "+f"(c[1]), "+f"(c[2]), "+f"(c[3])
        : "r"(a[0]), "r"(a[1]), "r"(a[2]), "r"(a[3]), "r"(b[0]), "r"(b[1]));
}
__device__ __forceinline__ void cp_async16(uint32_t dst, const void* src) {
    asm volatile("cp.async.cg.shared.global [%0], [%1], 16;" :: "r"(dst), "l"(src));
}
#define CP_COMMIT() asm volatile("cp.async.commit_group;" ::: "memory")
#define CP_WAIT0()  asm volatile("cp.async.wait_group 0;" ::: "memory")

// ====================================================================
// Kernel 0a: generic fp32 -> half (8 elems/thread)
// ====================================================================
__global__ void cvt_f2h_kernel(const float* __restrict__ src, __half* __restrict__ dst)
{
    size_t i = ((size_t)blockIdx.x * 256 + threadIdx.x) * 8;
    float4 v0 = *reinterpret_cast<const float4*>(src + i);
    float4 v1 = *reinterpret_cast<const float4*>(src + i + 4);
    *reinterpret_cast<uint4*>(dst + i) = f8_to_h8(v0, v1);
}

// ====================================================================
// Kernel 1: router — exact fp32 (must match reference top-k bitwise)
// ====================================================================
__global__ void router_kernel(const float* __restrict__ x,
                              const float* __restrict__ w_router,
                              const float* __restrict__ bias,
                              float* __restrict__ logits_out,
                              float* __restrict__ idx_out)
{
    int t = blockIdx.x;
    __shared__ alignas(16) float sx[HH];
    __shared__ float slog[EE];
    __shared__ float saff[EE];
    __shared__ float ssel[EE];

    const float* xr = x + (size_t)t * HH;
    for (int i = threadIdx.x; i < HH; i += blockDim.x) sx[i] = xr[i];
    __syncthreads();

    int warp = threadIdx.x >> 5;
    int lane = threadIdx.x & 31;

    for (int e = warp * 8; e < warp * 8 + 8; ++e) {
        const float* wr = w_router + (size_t)e * HH;
        float s = 0.f;
        for (int h = lane; h < HH; h += 32) s += sx[h] * wr[h];
        #pragma unroll
        for (int o = 16; o; o >>= 1) s += __shfl_xor_sync(0xffffffffu, s, o);
        if (lane == 0) {
            slog[e] = s;
            if (logits_out) logits_out[(size_t)t * EE + e] = s;
        }
    }
    __syncthreads();

    if (warp == 0) {
        for (int e = lane; e < EE; e += 32) {
            float l = slog[e];
            float a = 1.0f / (1.0f + expf(-l));
            saff[e] = a;
            ssel[e] = a + bias[e];
        }
        __syncwarp();

        int sel_idx[KK];
        #pragma unroll
        for (int k = 0; k < KK; ++k) {
            float v  = ssel[lane];      int id = lane;
            float v2 = ssel[lane + 32];
            if (v2 > v) { v = v2; id = lane + 32; }
            #pragma unroll
            for (int o = 16; o; o >>= 1) {
                float ov = __shfl_xor_sync(0xffffffffu, v, o);
                int   oi = __shfl_xor_sync(0xffffffffu, id, o);
                if (ov > v || (ov == v && oi < id)) { v = ov; id = oi; }
            }
            sel_idx[k] = id;
            if (lane == 0) ssel[id] = -INFINITY;
            __syncwarp();
        }

        if (lane == 0) {
            float wsum = 0.f;
            float wv[KK];
            #pragma unroll
            for (int k = 0; k < KK; ++k) { wv[k] = saff[sel_idx[k]]; wsum += wv[k]; }
            #pragma unroll
            for (int k = 0; k < KK; ++k) {
                g_expert_index[t * KK + k] = sel_idx[k];
                g_weights[t * KK + k]      = wv[k] / wsum;
                if (idx_out) idx_out[(size_t)t * KK + k] = (float)sel_idx[k];
            }
        }
    }
}

// ====================================================================
// Kernel 2: slot assignment (exact order of flattened [t,k])
// ====================================================================
__global__ void pos_kernel()
{
    int e   = blockIdx.x;
    int tid = threadIdx.x;
    const int NP    = TT * KK;
    const int chunk = NP / 256;
    __shared__ int scnt[256];

    int base = tid * chunk;
    int c = 0;
    for (int j = 0; j < chunk; ++j)
        if (g_expert_index[base + j] == e) c++;
    scnt[tid] = c;
    __syncthreads();

    if (tid == 0) {
        int run = 0;
        for (int i = 0; i < 256; ++i) { int v = scnt[i]; scnt[i] = run; run += v; }
        g_count[e] = run;
    }
    __syncthreads();

    int off = scnt[tid];
    for (int j = 0; j < chunk; ++j) {
        int i = base + j;
        if (g_expert_index[i] == e) {
            g_pair_pos[i] = off;
            if (off < CC) g_row_token[e * CC + off] = i / KK;
            off++;
        }
    }
}

// ====================================================================
// Kernel 3: gate+up GEMM + SiLU*u -> hbuf(half)  (mma.sync fp16 k16)
// CTA: M=128, N=64 (gate+up).  BK=64, double-buffered, ALL cp.async.
// A tile: [128][64h] stride 144B.  Bg/Bu: [64k][64h] stride 144B.
// Layout: A0=0(18432) A1=18432, Bg0=36864(9216) Bg1=46080,
//         Bu0=55296 Bu1=64512; total 73728.
// Loaders: all 256 threads do A (4 cp16); tid<128 Bg, tid>=128 Bu (4 cp16).
// grid = (CC/128=8 [m fastest], FF/64=8, EE)
// ====================================================================
__global__ void __launch_bounds__(256, 2) gemm1_mma()
{
    const int e  = blockIdx.z;
    const int m0 = blockIdx.x * 128;
    const int n0 = blockIdx.y * 64;

    int cnt = g_count[e];
    cnt = (cnt < CC) ? cnt : CC;
    if (m0 >= cnt) return;

    extern __shared__ unsigned char sbuf[];
    __shared__ int stok[128];

    const int tid  = threadIdx.x;
    const int wid  = tid >> 5;
    const int lane = tid & 31;
    const int wm   = wid >> 1;      // 0..3
    const int wn   = wid & 1;       // 0..1

    if (tid < 128) {
        int slot = m0 + tid;
        if (slot >= cnt) slot = cnt - 1;
        stok[tid] = g_row_token[e * CC + slot];
    }
    __syncthreads();

    const uint32_t sA = smem_to_u32(sbuf);

    // ---- loader constants ----
    // A: row = tid>>1, 64B chunk = (tid&1)
    const __half* a_src = g_xh + (size_t)stok[tid >> 1] * HH + (tid & 1) * 32;
    const uint32_t a_dst = sA + (tid >> 1) * 144 + (tid & 1) * 64;
    // B: half the threads each: row = (tid&127)>>1 (0..63), 64B chunk (tid&1)
    const int brow = (tid & 127) >> 1;
    const __half* b_src = ((tid < 128) ? g_wgh : g_wuh) +
                          ((size_t)e * HH + brow) * FF + n0 + (tid & 1) * 32;
    const uint32_t b_dst = sA + ((tid < 128) ? 36864u : 55296u) +
                           brow * 144 + (tid & 1) * 64;

    // ---- fragment address constants ----
    const int fa_row  = lane & 15;
    const int fa_koff = (lane >> 4) * 16;
    const int fb_noff = (wn * 32 + (lane >> 4) * 8) * 2;

    float accg[2][4][4];
    float accu[2][4][4];
    #pragma unroll
    for (int mi = 0; mi < 2; ++mi)
        #pragma unroll
        for (int nj = 0; nj < 4; ++nj)
            #pragma unroll
            for (int qq = 0; qq < 4; ++qq) { accg[mi][nj][qq] = 0.f; accu[mi][nj][qq] = 0.f; }

    // ---- prologue: chunk 0 ----
    {
        #pragma unroll
        for (int c = 0; c < 4; ++c) cp_async16(a_dst + c * 16, a_src + c * 8);
        #pragma unroll
        for (int c = 0; c < 4; ++c) cp_async16(b_dst + c * 16, b_src + c * 8);
        CP_COMMIT();
    }
    CP_WAIT0();
    __syncthreads();

    const int NK = HH / 64;   // 16
    for (int kc = 0; kc < NK; ++kc) {
        const int cur = kc & 1;
        const bool has_next = (kc + 1 < NK);
        if (has_next) {
            const int k0 = (kc + 1) * 64;
            const uint32_t Ad = a_dst + (cur ^ 1) * 18432;
            const uint32_t Bd = b_dst + (cur ^ 1) * 9216;
            #pragma unroll
            for (int c = 0; c < 4; ++c) cp_async16(Ad + c * 16, a_src + k0 + c * 8);
            #pragma unroll
            for (int c = 0; c < 4; ++c)
                cp_async16(Bd + c * 16, b_src + (size_t)k0 * FF + c * 8);
            CP_COMMIT();
        }

        // ---- compute current chunk: 4 ks of k16 ----
        const uint32_t Ab  = sA + cur * 18432;
        const uint32_t Bgb = sA + 36864 + cur * 9216;
        const uint32_t Bub = sA + 55296 + cur * 9216;
        #pragma unroll
        for (int ks = 0; ks < 4; ++ks) {
            uint32_t a[2][4];
            #pragma unroll
            for (int mi = 0; mi < 2; ++mi)
                ldm_x4(a[mi], Ab + (wm * 32 + mi * 16 + fa_row) * 144 + ks * 32 + fa_koff);
            #pragma unroll
            for (int pf = 0; pf < 2; ++pf) {
                uint32_t bg[4], bu[4];
                int boff = (ks * 16 + fa_row) * 144 + fb_noff + pf * 32;
                ldm_x4t(bg, Bgb + boff);
                ldm_x4t(bu, Bub + boff);
                #pragma unroll
                for (int mi = 0; mi < 2; ++mi) {
                    mma_f16(accg[mi][pf * 2 + 0], a[mi], bg + 0);
                    mma_f16(accg[mi][pf * 2 + 1], a[mi], bg + 2);
                    mma_f16(accu[mi][pf * 2 + 0], a[mi], bu + 0);
                    mma_f16(accu[mi][pf * 2 + 1], a[mi], bu + 2);
                }
            }
        }

        CP_WAIT0();
        __syncthreads();
    }

    // ---- epilogue: h = silu(g) * u -> half ----
    const int frow = lane >> 2;
    const int fcol = (lane & 3) * 2;
    #pragma unroll
    for (int mi = 0; mi < 2; ++mi) {
        #pragma unroll
        for (int nj = 0; nj < 4; ++nj) {
            int m = m0 + wm * 32 + mi * 16 + frow;
            int n = n0 + wn * 32 + nj * 8 + fcol;
            #pragma unroll
            for (int half = 0; half < 2; ++half) {
                float g0 = accg[mi][nj][half * 2 + 0];
                float g1 = accg[mi][nj][half * 2 + 1];
                float u0 = accu[mi][nj][half * 2 + 0];
                float u1 = accu[mi][nj][half * 2 + 1];
                float h0 = (g0 / (1.0f + expf(-g0))) * u0;
                float h1 = (g1 / (1.0f + expf(-g1))) * u1;
                *reinterpret_cast<__half2*>(
                    &g_hbuf[((size_t)e * CC + m + half * 8) * FF + n]) =
                    __floats2half2_rn(h0, h1);
            }
        }
    }
}

// ====================================================================
// Kernel 4: down GEMM: hbuf(half) x wdh(half) -> obuf(half)
// CTA: M=128, N=128.  BK=64, double-buffered, ALL cp.async.
// A tile: [128][64h] stride 144B.  B tile: [64k][128h] stride 272B.
// Layout: A0=0(18432) A1=18432, B0=36864(17408) B1=54272; total 71680.
// Loaders: A row=tid>>1, chunk tid&1 (4 cp16); B row=tid>>2, chunk tid&3 (4 cp16).
// grid = (CC/128=8 [m fastest], HH/128=8, EE)
// ====================================================================
__global__ void __launch_bounds__(256, 2) gemm2_mma()
{
    const int e  = blockIdx.z;
    const int m0 = blockIdx.x * 128;
    const int n0 = blockIdx.y * 128;

    int cnt = g_count[e];
    cnt = (cnt < CC) ? cnt : CC;
    if (m0 >= cnt) return;

    extern __shared__ unsigned char sbuf[];

    const int tid  = threadIdx.x;
    const int wid  = tid >> 5;
    const int lane = tid & 31;
    const int wm   = wid >> 1;
    const int wn   = wid & 1;

    const uint32_t sA = smem_to_u32(sbuf);

    const __half* a_src = g_hbuf + ((size_t)e * CC + m0 + (tid >> 1)) * FF + (tid & 1) * 32;
    const uint32_t a_dst = sA + (tid >> 1) * 144 + (tid & 1) * 64;
    const __half* b_src = g_wdh + ((size_t)e * FF + (tid >> 2)) * HH + n0 + (tid & 3) * 32;
    const uint32_t b_dst = sA + 36864 + (tid >> 2) * 272 + (tid & 3) * 64;

    const int fa_row  = lane & 15;
    const int fa_koff = (lane >> 4) * 16;
    const int fb_noff = (wn * 64 + (lane >> 4) * 8) * 2;

    float acc[2][8][4];
    #pragma unroll
    for (int mi = 0; mi < 2; ++mi)
        #pragma unroll
        for (int nj = 0; nj < 8; ++nj)
            #pragma unroll
            for (int qq = 0; qq < 4; ++qq) acc[mi][nj][qq] = 0.f;

    // ---- prologue chunk 0 ----
    {
        #pragma unroll
        for (int c = 0; c < 4; ++c) cp_async16(a_dst + c * 16, a_src + c * 8);
        #pragma unroll
        for (int c = 0; c < 4; ++c) cp_async16(b_dst + c * 16, b_src + c * 8);
        CP_COMMIT();
    }
    CP_WAIT0();
    __syncthreads();

    const int NK = FF / 64;   // 8
    for (int kc = 0; kc < NK; ++kc) {
        const int cur = kc & 1;
        const bool has_next = (kc + 1 < NK);
        if (has_next) {
            const int k0 = (kc + 1) * 64;
            const uint32_t Ad = a_dst + (cur ^ 1) * 18432;
            const uint32_t Bd = b_dst + (cur ^ 1) * 17408;
            #pragma unroll
            for (int c = 0; c < 4; ++c) cp_async16(Ad + c * 16, a_src + k0 + c * 8);
            #pragma unroll
            for (int c = 0; c < 4; ++c)
                cp_async16(Bd + c * 16, b_src + (size_t)k0 * HH + c * 8);
            CP_COMMIT();
        }

        const uint32_t Ab = sA + cur * 18432;
        const uint32_t Bb = sA + 36864 + cur * 17408;
        #pragma unroll
        for (int ks = 0; ks < 4; ++ks) {
            uint32_t a[2][4];
            #pragma unroll
            for (int mi = 0; mi < 2; ++mi)
                ldm_x4(a[mi], Ab + (wm * 32 + mi * 16 + fa_row) * 144 + ks * 32 + fa_koff);
            #pragma unroll
            for (int pf = 0; pf < 4; ++pf) {
                uint32_t b[4];
                ldm_x4t(b, Bb + (ks * 16 + fa_row) * 272 + fb_noff + pf * 32);
                #pragma unroll
                for (int mi = 0; mi < 2; ++mi) {
                    mma_f16(acc[mi][pf * 2 + 0], a[mi], b + 0);
                    mma_f16(acc[mi][pf * 2 + 1], a[mi], b + 2);
                }
            }
        }

        CP_WAIT0();
        __syncthreads();
    }

    const int frow = lane >> 2;
    const int fcol = (lane & 3) * 2;
    #pragma unroll
    for (int mi = 0; mi < 2; ++mi) {
        #pragma unroll
        for (int nj = 0; nj < 8; ++nj) {
            int m = m0 + wm * 32 + mi * 16 + frow;
            int n = n0 + wn * 64 + nj * 8 + fcol;
            #pragma unroll
            for (int half = 0; half < 2; ++half) {
                *reinterpret_cast<__half2*>(
                    &g_obuf[((size_t)e * CC + m + half * 8) * HH + n]) =
                    __floats2half2_rn(acc[mi][nj][half * 2 + 0],
                                      acc[mi][nj][half * 2 + 1]);
            }
        }
    }
}

// ====================================================================
// Kernel 5: combine — y[t] = sum_k w[t,k] * obuf[row(t,k)]  (obuf half)
// ====================================================================
__global__ void combine_kernel(float* __restrict__ y)
{
    int t = blockIdx.x;
    __shared__ int   srow[KK];
    __shared__ float sw[KK];
    if (threadIdx.x < KK) {
        int i = t * KK + threadIdx.x;
        int e = g_expert_index[i];
        int p = g_pair_pos[i];
        srow[threadIdx.x] = (p < CC) ? (e * CC + p) : -1;
        sw[threadIdx.x]   = g_weights[i];
    }
    __syncthreads();

    const int h0 = threadIdx.x * 4;     // 256 threads x 4 = 1024
    float a0 = 0.f, a1 = 0.f, a2 = 0.f, a3 = 0.f;
    #pragma unroll
    for (int k = 0; k < KK; ++k) {
        int r = srow[k];
        if (r >= 0) {
            float wk = sw[k];
            uint2 v = *reinterpret_cast<const uint2*>(&g_obuf[(size_t)r * HH + h0]);
            __half2 p0 = *reinterpret_cast<__half2*>(&v.x);
            __half2 p1 = *reinterpret_cast<__half2*>(&v.y);
            float2 f0 = __half22float2(p0);
            float2 f1 = __half22float2(p1);
            a0 += wk * f0.x; a1 += wk * f0.y;
            a2 += wk * f1.x; a3 += wk * f1.y;
        }
    }
    *reinterpret_cast<float4*>(&y[(size_t)t * HH + h0]) = make_float4(a0, a1, a2, a3);
}

// ====================================================================
extern "C" void kernel_launch(void* const* d_in, const int* in_sizes, int n_in,
                              void* d_out, int out_size)
{
    const float* x        = (const float*)d_in[0];
    const float* w_router = (const float*)d_in[1];
    const float* bias     = (const float*)d_in[2];
    const float* w_gate   = (const float*)d_in[3];
    const float* w_up     = (const float*)d_in[4];
    const float* w_down   = (const float*)d_in[5];

    float* y = (float*)d_out;
    float* logits_out = nullptr;
    float* idx_out    = nullptr;
    long long base = (long long)TT * HH;
    if ((long long)out_size >= base + (long long)TT * EE)
        logits_out = y + base;
    if ((long long)out_size >= base + (long long)TT * EE + (long long)TT * KK)
        idx_out = y + base + (long long)TT * EE;

    __half* xh;  cudaGetSymbolAddress((void**)&xh,  g_xh);
    __half* wgh; cudaGetSymbolAddress((void**)&wgh, g_wgh);
    __half* wuh; cudaGetSymbolAddress((void**)&wuh, g_wuh);
    __half* wdh; cudaGetSymbolAddress((void**)&wdh, g_wdh);

    const int SMEM1 = 73728;
    const int SMEM2 = 71680;
    cudaFuncSetAttribute(gemm1_mma, cudaFuncAttributeMaxDynamicSharedMemorySize, SMEM1);
    cudaFuncSetAttribute(gemm2_mma, cudaFuncAttributeMaxDynamicSharedMemorySize, SMEM2);

    const int NW = EE * HH * FF;   // 33.55M elems per weight tensor
    cvt_f2h_kernel<<<(TT * HH) / (256 * 8), 256>>>(x, xh);
    cvt_f2h_kernel<<<NW / (256 * 8), 256>>>(w_gate, wgh);
    cvt_f2h_kernel<<<NW / (256 * 8), 256>>>(w_up,   wuh);
    cvt_f2h_kernel<<<NW / (256 * 8), 256>>>(w_down, wdh);

    router_kernel<<<TT, 256>>>(x, w_router, bias, logits_out, idx_out);
    pos_kernel<<<EE, 256>>>();
    gemm1_mma<<<dim3(CC / 128, FF / 64, EE), 256, SMEM1>>>();
    gemm2_mma<<<dim3(CC / 128, HH / 128, EE), 256, SMEM2>>>();
    combine_kernel<<<TT, 256>>>(y);
}

// round 13
// speedup vs baseline: 1.2255x; 1.2255x over previous
#include <cuda_runtime.h>
#include <cuda_fp16.h>
#include <math.h>
#include <stdint.h>

// Problem constants
#define TT 4096   // tokens = B*S
#define EE 64     // experts
#define KK 8      // top_k
#define HH 1024   // hidden
#define FF 512    // expert ffn
#define CC 1024   // capacity

// -------- scratch (__device__ globals; no allocation allowed) --------
__device__ int   g_expert_index[TT * KK];
__device__ float g_weights[TT * KK];
__device__ int   g_pair_pos[TT * KK];
__device__ int   g_row_token[EE * CC];
__device__ int   g_count[EE];
__device__ alignas(16) __half g_xh[(size_t)TT * HH];         // 8 MB  (x in half)
__device__ alignas(16) __half g_hbuf[(size_t)EE * CC * FF];  // 67 MB (half)
__device__ alignas(16) __half g_obuf[(size_t)EE * CC * HH];  // 134 MB (half)

// -------- helpers --------
__device__ __forceinline__ uint32_t smem_to_u32(const void* p) {
    uint32_t a;
    asm("{ .reg .u64 t; cvta.to.shared.u64 t, %1; cvt.u32.u64 %0, t; }"
        : "=r"(a) : "l"(p));
    return a;
}
__device__ __forceinline__ uint2 f4_to_h4(float4 v) {
    __half2 a = __floats2half2_rn(v.x, v.y);
    __half2 b = __floats2half2_rn(v.z, v.w);
    uint2 r;
    r.x = *reinterpret_cast<uint32_t*>(&a);
    r.y = *reinterpret_cast<uint32_t*>(&b);
    return r;
}
__device__ __forceinline__ void ldm_x4(uint32_t* r, uint32_t addr) {
    asm volatile("ldmatrix.sync.aligned.m8n8.x4.shared.b16 {%0,%1,%2,%3}, [%4];"
        : "=r"(r[0]), "=r"(r[1]), "=r"(r[2]), "=r"(r[3]) : "r"(addr));
}
__device__ __forceinline__ void ldm_x4t(uint32_t* r, uint32_t addr) {
    asm volatile("ldmatrix.sync.aligned.m8n8.x4.trans.shared.b16 {%0,%1,%2,%3}, [%4];"
        : "=r"(r[0]), "=r"(r[1]), "=r"(r[2]), "=r"(r[3]) : "r"(addr));
}
__device__ __forceinline__ void mma_f16(float* c, const uint32_t* a, const uint32_t* b) {
    asm volatile(
        "mma.sync.aligned.m16n8k16.row.col.f32.f16.f16.f32 "
        "{%0,%1,%2,%3},{%4,%5,%6,%7},{%8,%9},{%0,%1,%2,%3};"
        : "+f"(c[0]), "+f"(c[1]), "+f"(c[2]), "+f"(c[3])
        : "r"(a[0]), "r"(a[1]), "r"(a[2]), "r"(a[3]), "r"(b[0]), "r"(b[1]));
}
__device__ __forceinline__ void cp_async16(uint32_t dst, const void* src) {
    asm volatile("cp.async.cg.shared.global [%0], [%1], 16;" :: "r"(dst), "l"(src));
}
#define CP_COMMIT() asm volatile("cp.async.commit_group;" ::: "memory")
#define CP_WAIT0()  asm volatile("cp.async.wait_group 0;" ::: "memory")

// ====================================================================
// Kernel 0: x -> half
// ====================================================================
__global__ void cvt_x_kernel(const float* __restrict__ x)
{
    size_t i = ((size_t)blockIdx.x * 256 + threadIdx.x) * 8;
    float4 v0 = *reinterpret_cast<const float4*>(x + i);
    float4 v1 = *reinterpret_cast<const float4*>(x + i + 4);
    uint2 a = f4_to_h4(v0);
    uint2 b = f4_to_h4(v1);
    uint4 o; o.x = a.x; o.y = a.y; o.z = b.x; o.w = b.y;
    *reinterpret_cast<uint4*>(g_xh + i) = o;
}

// ====================================================================
// Kernel 1: router — 8 tokens per block, w_router tiled through SMEM.
// L2 traffic for w_router: 512 blocks x 256KB = 134MB (was 1GB).
// Each warp owns one token; lane owns experts {lane, lane+32}.
// ====================================================================
__global__ void __launch_bounds__(256) router_kernel(
    const float* __restrict__ x,
    const float* __restrict__ w_router,
    const float* __restrict__ bias,
    float* __restrict__ logits_out,
    float* __restrict__ idx_out)
{
    __shared__ float swT[128][65];   // w_router chunk transposed: [h][e], 33KB
    __shared__ float sx[8][128];     // 8 token rows, current h-chunk
    __shared__ float ssel[8][64];
    __shared__ float saff[8][64];

    const int tid  = threadIdx.x;
    const int warp = tid >> 5;
    const int lane = tid & 31;
    const int t0   = blockIdx.x * 8;
    const int t    = t0 + warp;

    float acc0 = 0.f, acc1 = 0.f;

    for (int hc = 0; hc < HH / 128; ++hc) {
        // load w_router[0:64][hc*128 : hc*128+128] transposed into swT[h][e]
        // 256 threads: row e = tid>>2 (0..63), 8 float4 along h
        {
            const int e  = tid >> 2;
            const float* wr = w_router + (size_t)e * HH + hc * 128;
            #pragma unroll
            for (int p = 0; p < 8; ++p) {
                int h4 = (tid & 3) + p * 4;           // 0..31
                float4 v = *reinterpret_cast<const float4*>(wr + h4 * 4);
                swT[h4 * 4 + 0][e] = v.x;
                swT[h4 * 4 + 1][e] = v.y;
                swT[h4 * 4 + 2][e] = v.z;
                swT[h4 * 4 + 3][e] = v.w;
            }
        }
        // load 8 token rows' h-chunk
        {
            const int r  = tid >> 5;
            const int c4 = tid & 31;
            float4 v = *reinterpret_cast<const float4*>(
                x + (size_t)(t0 + r) * HH + hc * 128 + c4 * 4);
            *reinterpret_cast<float4*>(&sx[r][c4 * 4]) = v;
        }
        __syncthreads();

        #pragma unroll 4
        for (int h = 0; h < 128; ++h) {
            float xv = sx[warp][h];
            acc0 += xv * swT[h][lane];
            acc1 += xv * swT[h][lane + 32];
        }
        __syncthreads();
    }

    // logits out
    if (logits_out) {
        logits_out[(size_t)t * EE + lane]      = acc0;
        logits_out[(size_t)t * EE + lane + 32] = acc1;
    }

    // affinities + biased selection scores
    {
        float a0 = 1.0f / (1.0f + expf(-acc0));
        float a1 = 1.0f / (1.0f + expf(-acc1));
        saff[warp][lane]      = a0;
        saff[warp][lane + 32] = a1;
        ssel[warp][lane]      = a0 + bias[lane];
        ssel[warp][lane + 32] = a1 + bias[lane + 32];
    }
    __syncwarp();

    // per-warp top-8 (max with tie -> lowest index), zap-and-repeat
    int sel_idx[KK];
    #pragma unroll
    for (int k = 0; k < KK; ++k) {
        float v  = ssel[warp][lane];      int id = lane;
        float v2 = ssel[warp][lane + 32];
        if (v2 > v) { v = v2; id = lane + 32; }
        #pragma unroll
        for (int o = 16; o; o >>= 1) {
            float ov = __shfl_xor_sync(0xffffffffu, v, o);
            int   oi = __shfl_xor_sync(0xffffffffu, id, o);
            if (ov > v || (ov == v && oi < id)) { v = ov; id = oi; }
        }
        sel_idx[k] = id;
        if (lane == 0) ssel[warp][id] = -INFINITY;
        __syncwarp();
    }

    if (lane == 0) {
        float wsum = 0.f;
        float wv[KK];
        #pragma unroll
        for (int k = 0; k < KK; ++k) { wv[k] = saff[warp][sel_idx[k]]; wsum += wv[k]; }
        #pragma unroll
        for (int k = 0; k < KK; ++k) {
            g_expert_index[t * KK + k] = sel_idx[k];
            g_weights[t * KK + k]      = wv[k] / wsum;
            if (idx_out) idx_out[(size_t)t * KK + k] = (float)sel_idx[k];
        }
    }
}

// ====================================================================
// Kernel 2: slot assignment (exact order of flattened [t,k])
// ====================================================================
__global__ void pos_kernel()
{
    int e   = blockIdx.x;
    int tid = threadIdx.x;
    const int NP    = TT * KK;
    const int chunk = NP / 256;
    __shared__ int scnt[256];

    int base = tid * chunk;
    int c = 0;
    for (int j = 0; j < chunk; ++j)
        if (g_expert_index[base + j] == e) c++;
    scnt[tid] = c;
    __syncthreads();

    if (tid == 0) {
        int run = 0;
        for (int i = 0; i < 256; ++i) { int v = scnt[i]; scnt[i] = run; run += v; }
        g_count[e] = run;
    }
    __syncthreads();

    int off = scnt[tid];
    for (int j = 0; j < chunk; ++j) {
        int i = base + j;
        if (g_expert_index[i] == e) {
            g_pair_pos[i] = off;
            if (off < CC) g_row_token[e * CC + off] = i / KK;
            off++;
        }
    }
}

// ====================================================================
// Kernel 3: gate+up GEMM + SiLU*u -> hbuf(half)  (mma.sync fp16 k16)
// CTA: M=128, N=64 (gate+up).  BK=32, double-buffered.
// A via cp.async from g_xh; B fp32->half packed STS.128.
// A tile: [128 rows][32 halves], stride 80B.  B tiles: [32 k][64 n], 144B.
// grid = (CC/128=8 [m fastest], FF/64=8, EE)
// ====================================================================
__global__ void __launch_bounds__(256, 2) gemm1_mma(const float* __restrict__ w_gate,
                                                    const float* __restrict__ w_up)
{
    const int e  = blockIdx.z;
    const int m0 = blockIdx.x * 128;
    const int n0 = blockIdx.y * 64;

    int cnt = g_count[e];
    cnt = (cnt < CC) ? cnt : CC;
    if (m0 >= cnt) return;

    // A0=0(10240) A1=10240, Bg0=20480(4608) Bg1=25088, Bu0=29696 Bu1=34304
    __shared__ alignas(16) unsigned char sbuf[38912];
    __shared__ int stok[128];

    const int tid  = threadIdx.x;
    const int wid  = tid >> 5;
    const int lane = tid & 31;
    const int wm   = wid >> 1;      // 0..3
    const int wn   = wid & 1;       // 0..1

    if (tid < 128) {
        int slot = m0 + tid;
        if (slot >= cnt) slot = cnt - 1;
        stok[tid] = g_row_token[e * CC + slot];
    }
    __syncthreads();

    const uint32_t sA = smem_to_u32(sbuf);

    // ---- loader constants ----
    const int a_row = tid >> 2;                 // 0..63 (+p*64)
    const int a_q4  = tid & 3;                  // 16B chunk within 64B row
    const int b_krow = tid >> 3;                // 0..31
    const int b_n8   = tid & 7;                 // 8 floats each

    const float* wg_base = w_gate + (size_t)e * HH * FF + n0;
    const float* wu_base = w_up   + (size_t)e * HH * FF + n0;
    const __half* xrow0 = g_xh + (size_t)stok[a_row] * HH;
    const __half* xrow1 = g_xh + (size_t)stok[a_row + 64] * HH;

    // ---- fragment address constants ----
    const int fa_row  = (lane & 7) + ((lane >> 3) & 1) * 8;
    const int fa_koff = (lane >> 4) * 16;
    const int fb_k    = (lane & 7) + ((lane >> 3) & 1) * 8;
    const int fb_noff = (wn * 32 + (lane >> 4) * 8) * 2;

    float accg[2][4][4];
    float accu[2][4][4];
    #pragma unroll
    for (int mi = 0; mi < 2; ++mi)
        #pragma unroll
        for (int nj = 0; nj < 4; ++nj)
            #pragma unroll
            for (int qq = 0; qq < 4; ++qq) { accg[mi][nj][qq] = 0.f; accu[mi][nj][qq] = 0.f; }

    float4 bg_pre[2], bu_pre[2];

    // ---- prologue: chunk 0 ----
    {
        const uint32_t Ad = sA + a_row * 80 + a_q4 * 16;
        cp_async16(Ad,            xrow0 + a_q4 * 8);
        cp_async16(Ad + 64 * 80,  xrow1 + a_q4 * 8);
        CP_COMMIT();
        size_t boff = (size_t)b_krow * FF + b_n8 * 8;
        bg_pre[0] = *reinterpret_cast<const float4*>(wg_base + boff);
        bg_pre[1] = *reinterpret_cast<const float4*>(wg_base + boff + 4);
        bu_pre[0] = *reinterpret_cast<const float4*>(wu_base + boff);
        bu_pre[1] = *reinterpret_cast<const float4*>(wu_base + boff + 4);
        int off = b_krow * 144 + b_n8 * 16;
        uint2 lo = f4_to_h4(bg_pre[0]), hi = f4_to_h4(bg_pre[1]);
        *reinterpret_cast<uint4*>(sbuf + 20480 + off) = make_uint4(lo.x, lo.y, hi.x, hi.y);
        lo = f4_to_h4(bu_pre[0]); hi = f4_to_h4(bu_pre[1]);
        *reinterpret_cast<uint4*>(sbuf + 29696 + off) = make_uint4(lo.x, lo.y, hi.x, hi.y);
    }
    CP_WAIT0();
    __syncthreads();

    const int NK = HH / 32;   // 32
    for (int kc = 0; kc < NK; ++kc) {
        const int cur = kc & 1;
        const int has_next = (kc + 1 < NK);
        // issue async A + LDG B for next chunk
        if (has_next) {
            const int k0 = (kc + 1) * 32;
            const uint32_t Ad = sA + (cur ^ 1) * 10240 + a_row * 80 + a_q4 * 16;
            cp_async16(Ad,           xrow0 + k0 + a_q4 * 8);
            cp_async16(Ad + 64 * 80, xrow1 + k0 + a_q4 * 8);
            CP_COMMIT();
            size_t boff = (size_t)(k0 + b_krow) * FF + b_n8 * 8;
            bg_pre[0] = *reinterpret_cast<const float4*>(wg_base + boff);
            bg_pre[1] = *reinterpret_cast<const float4*>(wg_base + boff + 4);
            bu_pre[0] = *reinterpret_cast<const float4*>(wu_base + boff);
            bu_pre[1] = *reinterpret_cast<const float4*>(wu_base + boff + 4);
        }

        // compute current chunk (2 ks of k16)
        const uint32_t Ab  = sA + cur * 10240;
        const uint32_t Bgb = sA + 20480 + cur * 4608;
        const uint32_t Bub = sA + 29696 + cur * 4608;
        #pragma unroll
        for (int ks = 0; ks < 2; ++ks) {
            uint32_t a[2][4];
            #pragma unroll
            for (int mi = 0; mi < 2; ++mi)
                ldm_x4(a[mi], Ab + (wm * 32 + mi * 16 + fa_row) * 80 + ks * 32 + fa_koff);
            #pragma unroll
            for (int pf = 0; pf < 2; ++pf) {
                uint32_t bg[4], bu[4];
                int boff = (ks * 16 + fb_k) * 144 + fb_noff + pf * 32;
                ldm_x4t(bg, Bgb + boff);
                ldm_x4t(bu, Bub + boff);
                #pragma unroll
                for (int mi = 0; mi < 2; ++mi) {
                    mma_f16(accg[mi][pf * 2 + 0], a[mi], bg + 0);
                    mma_f16(accg[mi][pf * 2 + 1], a[mi], bg + 2);
                    mma_f16(accu[mi][pf * 2 + 0], a[mi], bu + 0);
                    mma_f16(accu[mi][pf * 2 + 1], a[mi], bu + 2);
                }
            }
        }

        if (has_next) {
            unsigned char* nbg = sbuf + 20480 + (cur ^ 1) * 4608;
            unsigned char* nbu = sbuf + 29696 + (cur ^ 1) * 4608;
            int off = b_krow * 144 + b_n8 * 16;
            uint2 lo = f4_to_h4(bg_pre[0]), hi = f4_to_h4(bg_pre[1]);
            *reinterpret_cast<uint4*>(nbg + off) = make_uint4(lo.x, lo.y, hi.x, hi.y);
            lo = f4_to_h4(bu_pre[0]); hi = f4_to_h4(bu_pre[1]);
            *reinterpret_cast<uint4*>(nbu + off) = make_uint4(lo.x, lo.y, hi.x, hi.y);
        }
        CP_WAIT0();
        __syncthreads();
    }

    // ---- epilogue: h = silu(g) * u -> half ----
    const int frow = lane >> 2;
    const int fcol = (lane & 3) * 2;
    #pragma unroll
    for (int mi = 0; mi < 2; ++mi) {
        #pragma unroll
        for (int nj = 0; nj < 4; ++nj) {
            int m = m0 + wm * 32 + mi * 16 + frow;
            int n = n0 + wn * 32 + nj * 8 + fcol;
            #pragma unroll
            for (int half = 0; half < 2; ++half) {
                float g0 = accg[mi][nj][half * 2 + 0];
                float g1 = accg[mi][nj][half * 2 + 1];
                float u0 = accu[mi][nj][half * 2 + 0];
                float u1 = accu[mi][nj][half * 2 + 1];
                float h0 = (g0 / (1.0f + expf(-g0))) * u0;
                float h1 = (g1 / (1.0f + expf(-g1))) * u1;
                *reinterpret_cast<__half2*>(
                    &g_hbuf[((size_t)e * CC + m + half * 8) * FF + n]) =
                    __floats2half2_rn(h0, h1);
            }
        }
    }
}

// ====================================================================
// Kernel 4: down GEMM: hbuf(half) x w_down -> obuf(half)
// CTA: M=128, N=128.  BK=32, double-buffered.
// A via cp.async; B fp32->half packed STS.128.
// A tile: [128][32 halves] stride 80B.  B tile: [32 k][128 n] stride 272B.
// grid = (CC/128=8 [m fastest], HH/128=8, EE)
// ====================================================================
__global__ void __launch_bounds__(256, 2) gemm2_mma(const float* __restrict__ w_down)
{
    const int e  = blockIdx.z;
    const int m0 = blockIdx.x * 128;
    const int n0 = blockIdx.y * 128;

    int cnt = g_count[e];
    cnt = (cnt < CC) ? cnt : CC;
    if (m0 >= cnt) return;

    // A0=0(10240) A1=10240, B0=20480(8704) B1=29184; total 37888
    __shared__ alignas(16) unsigned char sbuf[37888];

    const int tid  = threadIdx.x;
    const int wid  = tid >> 5;
    const int lane = tid & 31;
    const int wm   = wid >> 1;
    const int wn   = wid & 1;

    const int a_row = tid >> 2;                 // 0..63 (+p*64)
    const int a_q4  = tid & 3;
    const int b_krow = tid >> 4;                // 0..15 (+p*16)
    const int b_n8   = tid & 15;                // 8 floats

    const __half* a_base = g_hbuf + ((size_t)e * CC + m0) * FF;
    const float*  b_base = w_down + (size_t)e * FF * HH + n0;

    const uint32_t sA = smem_to_u32(sbuf);

    const int fa_row  = (lane & 7) + ((lane >> 3) & 1) * 8;
    const int fa_koff = (lane >> 4) * 16;
    const int fb_k    = (lane & 7) + ((lane >> 3) & 1) * 8;
    const int fb_noff = (wn * 64 + (lane >> 4) * 8) * 2;

    float acc[2][8][4];
    #pragma unroll
    for (int mi = 0; mi < 2; ++mi)
        #pragma unroll
        for (int nj = 0; nj < 8; ++nj)
            #pragma unroll
            for (int qq = 0; qq < 4; ++qq) acc[mi][nj][qq] = 0.f;

    float4 b_pre[4];

    // ---- prologue chunk 0 ----
    {
        const uint32_t Ad = sA + a_row * 80 + a_q4 * 16;
        cp_async16(Ad,           a_base + (size_t)a_row * FF + a_q4 * 8);
        cp_async16(Ad + 64 * 80, a_base + (size_t)(a_row + 64) * FF + a_q4 * 8);
        CP_COMMIT();
        #pragma unroll
        for (int p = 0; p < 2; ++p) {
            size_t boff = (size_t)(b_krow + p * 16) * HH + b_n8 * 8;
            b_pre[p * 2 + 0] = *reinterpret_cast<const float4*>(b_base + boff);
            b_pre[p * 2 + 1] = *reinterpret_cast<const float4*>(b_base + boff + 4);
        }
        #pragma unroll
        for (int p = 0; p < 2; ++p) {
            int off = (b_krow + p * 16) * 272 + b_n8 * 16;
            uint2 lo = f4_to_h4(b_pre[p * 2 + 0]), hi = f4_to_h4(b_pre[p * 2 + 1]);
            *reinterpret_cast<uint4*>(sbuf + 20480 + off) = make_uint4(lo.x, lo.y, hi.x, hi.y);
        }
    }
    CP_WAIT0();
    __syncthreads();

    const int NK = FF / 32;   // 16
    for (int kc = 0; kc < NK; ++kc) {
        const int cur = kc & 1;
        const int has_next = (kc + 1 < NK);
        if (has_next) {
            const int k0 = (kc + 1) * 32;
            const uint32_t Ad = sA + (cur ^ 1) * 10240 + a_row * 80 + a_q4 * 16;
            cp_async16(Ad,           a_base + (size_t)a_row * FF + k0 + a_q4 * 8);
            cp_async16(Ad + 64 * 80, a_base + (size_t)(a_row + 64) * FF + k0 + a_q4 * 8);
            CP_COMMIT();
            #pragma unroll
            for (int p = 0; p < 2; ++p) {
                size_t boff = (size_t)(k0 + b_krow + p * 16) * HH + b_n8 * 8;
                b_pre[p * 2 + 0] = *reinterpret_cast<const float4*>(b_base + boff);
                b_pre[p * 2 + 1] = *reinterpret_cast<const float4*>(b_base + boff + 4);
            }
        }

        const uint32_t Ab = sA + cur * 10240;
        const uint32_t Bb = sA + 20480 + cur * 8704;
        #pragma unroll
        for (int ks = 0; ks < 2; ++ks) {
            uint32_t a[2][4];
            #pragma unroll
            for (int mi = 0; mi < 2; ++mi)
                ldm_x4(a[mi], Ab + (wm * 32 + mi * 16 + fa_row) * 80 + ks * 32 + fa_koff);
            #pragma unroll
            for (int pf = 0; pf < 4; ++pf) {
                uint32_t b[4];
                ldm_x4t(b, Bb + (ks * 16 + fb_k) * 272 + fb_noff + pf * 32);
                #pragma unroll
                for (int mi = 0; mi < 2; ++mi) {
                    mma_f16(acc[mi][pf * 2 + 0], a[mi], b + 0);
                    mma_f16(acc[mi][pf * 2 + 1], a[mi], b + 2);
                }
            }
        }

        if (has_next) {
            unsigned char* nb = sbuf + 20480 + (cur ^ 1) * 8704;
            #pragma unroll
            for (int p = 0; p < 2; ++p) {
                int off = (b_krow + p * 16) * 272 + b_n8 * 16;
                uint2 lo = f4_to_h4(b_pre[p * 2 + 0]), hi = f4_to_h4(b_pre[p * 2 + 1]);
                *reinterpret_cast<uint4*>(nb + off) = make_uint4(lo.x, lo.y, hi.x, hi.y);
            }
        }
        CP_WAIT0();
        __syncthreads();
    }

    const int frow = lane >> 2;
    const int fcol = (lane & 3) * 2;
    #pragma unroll
    for (int mi = 0; mi < 2; ++mi) {
        #pragma unroll
        for (int nj = 0; nj < 8; ++nj) {
            int m = m0 + wm * 32 + mi * 16 + frow;
            int n = n0 + wn * 64 + nj * 8 + fcol;
            #pragma unroll
            for (int half = 0; half < 2; ++half) {
                *reinterpret_cast<__half2*>(
                    &g_obuf[((size_t)e * CC + m + half * 8) * HH + n]) =
                    __floats2half2_rn(acc[mi][nj][half * 2 + 0],
                                      acc[mi][nj][half * 2 + 1]);
            }
        }
    }
}

// ====================================================================
// Kernel 5: combine — y[t] = sum_k w[t,k] * obuf[row(t,k)]  (obuf half)
// ====================================================================
__global__ void combine_kernel(float* __restrict__ y)
{
    int t = blockIdx.x;
    __shared__ int   srow[KK];
    __shared__ float sw[KK];
    if (threadIdx.x < KK) {
        int i = t * KK + threadIdx.x;
        int e = g_expert_index[i];
        int p = g_pair_pos[i];
        srow[threadIdx.x] = (p < CC) ? (e * CC + p) : -1;
        sw[threadIdx.x]   = g_weights[i];
    }
    __syncthreads();

    const int h0 = threadIdx.x * 4;     // 256 threads x 4 = 1024
    float a0 = 0.f, a1 = 0.f, a2 = 0.f, a3 = 0.f;
    #pragma unroll
    for (int k = 0; k < KK; ++k) {
        int r = srow[k];
        if (r >= 0) {
            float wk = sw[k];
            uint2 v = *reinterpret_cast<const uint2*>(&g_obuf[(size_t)r * HH + h0]);
            __half2 p0 = *reinterpret_cast<__half2*>(&v.x);
            __half2 p1 = *reinterpret_cast<__half2*>(&v.y);
            float2 f0 = __half22float2(p0);
            float2 f1 = __half22float2(p1);
            a0 += wk * f0.x; a1 += wk * f0.y;
            a2 += wk * f1.x; a3 += wk * f1.y;
        }
    }
    *reinterpret_cast<float4*>(&y[(size_t)t * HH + h0]) = make_float4(a0, a1, a2, a3);
}

// ====================================================================
extern "C" void kernel_launch(void* const* d_in, const int* in_sizes, int n_in,
                              void* d_out, int out_size)
{
    const float* x        = (const float*)d_in[0];
    const float* w_router = (const float*)d_in[1];
    const float* bias     = (const float*)d_in[2];
    const float* w_gate   = (const float*)d_in[3];
    const float* w_up     = (const float*)d_in[4];
    const float* w_down   = (const float*)d_in[5];

    float* y = (float*)d_out;
    float* logits_out = nullptr;
    float* idx_out    = nullptr;
    long long base = (long long)TT * HH;
    if ((long long)out_size >= base + (long long)TT * EE)
        logits_out = y + base;
    if ((long long)out_size >= base + (long long)TT * EE + (long long)TT * KK)
        idx_out = y + base + (long long)TT * EE;

    cvt_x_kernel<<<(TT * HH) / (256 * 8), 256>>>(x);
    router_kernel<<<TT / 8, 256>>>(x, w_router, bias, logits_out, idx_out);
    pos_kernel<<<EE, 256>>>();
    gemm1_mma<<<dim3(CC / 128, FF / 64, EE), 256>>>(w_gate, w_up);
    gemm2_mma<<<dim3(CC / 128, HH / 128, EE), 256>>>(w_down);
    combine_kernel<<<TT, 256>>>(y);
}

// round 14
// speedup vs baseline: 1.2733x; 1.0390x over previous
#include <cuda_runtime.h>
#include <cuda_fp16.h>
#include <math.h>
#include <stdint.h>

// Problem constants
#define TT 4096   // tokens = B*S
#define EE 64     // experts
#define KK 8      // top_k
#define HH 1024   // hidden
#define FF 512    // expert ffn
#define CC 1024   // capacity

// -------- scratch (__device__ globals; no allocation allowed) --------
__device__ int   g_expert_index[TT * KK];
__device__ float g_weights[TT * KK];
__device__ int   g_pair_pos[TT * KK];
__device__ int   g_row_token[EE * CC];
__device__ int   g_count[EE];
__device__ alignas(16) __half g_xh[(size_t)TT * HH];         // 8 MB  (x in half)
__device__ alignas(16) __half g_hbuf[(size_t)EE * CC * FF];  // 67 MB (half)
__device__ alignas(16) __half g_obuf[(size_t)EE * CC * HH];  // 134 MB (half)

// -------- helpers --------
__device__ __forceinline__ uint32_t smem_to_u32(const void* p) {
    uint32_t a;
    asm("{ .reg .u64 t; cvta.to.shared.u64 t, %1; cvt.u32.u64 %0, t; }"
        : "=r"(a) : "l"(p));
    return a;
}
__device__ __forceinline__ uint2 f4_to_h4(float4 v) {
    __half2 a = __floats2half2_rn(v.x, v.y);
    __half2 b = __floats2half2_rn(v.z, v.w);
    uint2 r;
    r.x = *reinterpret_cast<uint32_t*>(&a);
    r.y = *reinterpret_cast<uint32_t*>(&b);
    return r;
}
__device__ __forceinline__ void ldm_x4(uint32_t* r, uint32_t addr) {
    asm volatile("ldmatrix.sync.aligned.m8n8.x4.shared.b16 {%0,%1,%2,%3}, [%4];"
        : "=r"(r[0]), "=r"(r[1]), "=r"(r[2]), "=r"(r[3]) : "r"(addr));
}
__device__ __forceinline__ void ldm_x4t(uint32_t* r, uint32_t addr) {
    asm volatile("ldmatrix.sync.aligned.m8n8.x4.trans.shared.b16 {%0,%1,%2,%3}, [%4];"
        : "=r"(r[0]), "=r"(r[1]), "=r"(r[2]), "=r"(r[3]) : "r"(addr));
}
__device__ __forceinline__ void mma_f16(float* c, const uint32_t* a, const uint32_t* b) {
    asm volatile(
        "mma.sync.aligned.m16n8k16.row.col.f32.f16.f16.f32 "
        "{%0,%1,%2,%3},{%4,%5,%6,%7},{%8,%9},{%0,%1,%2,%3};"
        : "+f"(c[0]), "+f"(c[1]), "+f"(c[2]), "+f"(c[3])
        : "r"(a[0]), "r"(a[1]), "r"(a[2]), "r"(a[3]), "r"(b[0]), "r"(b[1]));
}
__device__ __forceinline__ void cp_async16(uint32_t dst, const void* src) {
    asm volatile("cp.async.cg.shared.global [%0], [%1], 16;" :: "r"(dst), "l"(src));
}
#define CP_COMMIT() asm volatile("cp.async.commit_group;" ::: "memory")
#define CP_WAIT1()  asm volatile("cp.async.wait_group 1;" ::: "memory")

// ====================================================================
// Kernel 1: router — 8 tokens/block, w_router tiled via SMEM.
// ALSO converts x -> g_xh (half) on the fly (replaces cvt_x kernel).
// ====================================================================
__global__ void __launch_bounds__(256) router_kernel(
    const float* __restrict__ x,
    const float* __restrict__ w_router,
    const float* __restrict__ bias,
    float* __restrict__ logits_out,
    float* __restrict__ idx_out)
{
    __shared__ float swT[128][65];   // w_router chunk transposed [h][e]
    __shared__ float sx[8][128];
    __shared__ float ssel[8][64];
    __shared__ float saff[8][64];

    const int tid  = threadIdx.x;
    const int warp = tid >> 5;
    const int lane = tid & 31;
    const int t0   = blockIdx.x * 8;
    const int t    = t0 + warp;

    float acc0 = 0.f, acc1 = 0.f;

    for (int hc = 0; hc < HH / 128; ++hc) {
        // w_router chunk transposed
        {
            const int e  = tid >> 2;
            const float* wr = w_router + (size_t)e * HH + hc * 128;
            #pragma unroll
            for (int p = 0; p < 8; ++p) {
                int h4 = (tid & 3) + p * 4;
                float4 v = *reinterpret_cast<const float4*>(wr + h4 * 4);
                swT[h4 * 4 + 0][e] = v.x;
                swT[h4 * 4 + 1][e] = v.y;
                swT[h4 * 4 + 2][e] = v.z;
                swT[h4 * 4 + 3][e] = v.w;
            }
        }
        // 8 token rows' chunk; fused fp32->half store to g_xh
        {
            const int r  = tid >> 5;
            const int c4 = tid & 31;
            size_t gidx = (size_t)(t0 + r) * HH + hc * 128 + c4 * 4;
            float4 v = *reinterpret_cast<const float4*>(x + gidx);
            *reinterpret_cast<float4*>(&sx[r][c4 * 4]) = v;
            *reinterpret_cast<uint2*>(g_xh + gidx) = f4_to_h4(v);
        }
        __syncthreads();

        #pragma unroll 4
        for (int h = 0; h < 128; ++h) {
            float xv = sx[warp][h];
            acc0 += xv * swT[h][lane];
            acc1 += xv * swT[h][lane + 32];
        }
        __syncthreads();
    }

    if (logits_out) {
        logits_out[(size_t)t * EE + lane]      = acc0;
        logits_out[(size_t)t * EE + lane + 32] = acc1;
    }

    {
        float a0 = 1.0f / (1.0f + expf(-acc0));
        float a1 = 1.0f / (1.0f + expf(-acc1));
        saff[warp][lane]      = a0;
        saff[warp][lane + 32] = a1;
        ssel[warp][lane]      = a0 + bias[lane];
        ssel[warp][lane + 32] = a1 + bias[lane + 32];
    }
    __syncwarp();

    int sel_idx[KK];
    #pragma unroll
    for (int k = 0; k < KK; ++k) {
        float v  = ssel[warp][lane];      int id = lane;
        float v2 = ssel[warp][lane + 32];
        if (v2 > v) { v = v2; id = lane + 32; }
        #pragma unroll
        for (int o = 16; o; o >>= 1) {
            float ov = __shfl_xor_sync(0xffffffffu, v, o);
            int   oi = __shfl_xor_sync(0xffffffffu, id, o);
            if (ov > v || (ov == v && oi < id)) { v = ov; id = oi; }
        }
        sel_idx[k] = id;
        if (lane == 0) ssel[warp][id] = -INFINITY;
        __syncwarp();
    }

    if (lane == 0) {
        float wsum = 0.f;
        float wv[KK];
        #pragma unroll
        for (int k = 0; k < KK; ++k) { wv[k] = saff[warp][sel_idx[k]]; wsum += wv[k]; }
        #pragma unroll
        for (int k = 0; k < KK; ++k) {
            g_expert_index[t * KK + k] = sel_idx[k];
            g_weights[t * KK + k]      = wv[k] / wsum;
            if (idx_out) idx_out[(size_t)t * KK + k] = (float)sel_idx[k];
        }
    }
}

// ====================================================================
// Kernel 2: slot assignment (exact order of flattened [t,k])
// ====================================================================
__global__ void pos_kernel()
{
    int e   = blockIdx.x;
    int tid = threadIdx.x;
    const int NP    = TT * KK;
    const int chunk = NP / 256;
    __shared__ int scnt[256];

    int base = tid * chunk;
    int c = 0;
    for (int j = 0; j < chunk; ++j)
        if (g_expert_index[base + j] == e) c++;
    scnt[tid] = c;
    __syncthreads();

    if (tid == 0) {
        int run = 0;
        for (int i = 0; i < 256; ++i) { int v = scnt[i]; scnt[i] = run; run += v; }
        g_count[e] = run;
    }
    __syncthreads();

    int off = scnt[tid];
    for (int j = 0; j < chunk; ++j) {
        int i = base + j;
        if (g_expert_index[i] == e) {
            g_pair_pos[i] = off;
            if (off < CC) g_row_token[e * CC + off] = i / KK;
            off++;
        }
    }
}

// ====================================================================
// Kernel 3: gate+up GEMM + SiLU*u -> hbuf(half)  (mma.sync fp16 k16)
// CTA: M=128, N=64 (gate+up).  BK=32.
// 3-stage A pipeline (cp.async, wait_group 1), 2-stage B (LDG->regs->STS).
// Dyn SMEM (bytes): A 3x10240 @0; Bg 2x4608 @30720; Bu 2x4608 @39936. 49152.
// grid = (CC/128=8 [m fastest], FF/64=8, EE)
// ====================================================================
__global__ void __launch_bounds__(256, 2) gemm1_mma(const float* __restrict__ w_gate,
                                                    const float* __restrict__ w_up)
{
    const int e  = blockIdx.z;
    const int m0 = blockIdx.x * 128;
    const int n0 = blockIdx.y * 64;

    int cnt = g_count[e];
    cnt = (cnt < CC) ? cnt : CC;
    if (m0 >= cnt) return;

    extern __shared__ unsigned char sbuf[];
    __shared__ int stok[128];

    const int tid  = threadIdx.x;
    const int wid  = tid >> 5;
    const int lane = tid & 31;
    const int wm   = wid >> 1;      // 0..3
    const int wn   = wid & 1;       // 0..1

    if (tid < 128) {
        int slot = m0 + tid;
        if (slot >= cnt) slot = cnt - 1;
        stok[tid] = g_row_token[e * CC + slot];
    }
    __syncthreads();

    const uint32_t sA = smem_to_u32(sbuf);

    // loader constants
    const int a_row = tid >> 2;                 // 0..63 (+64)
    const int a_q4  = tid & 3;
    const int b_krow = tid >> 3;                // 0..31
    const int b_n8   = tid & 7;

    const float* wg_base = w_gate + (size_t)e * HH * FF + n0;
    const float* wu_base = w_up   + (size_t)e * HH * FF + n0;
    const __half* xrow0 = g_xh + (size_t)stok[a_row] * HH;
    const __half* xrow1 = g_xh + (size_t)stok[a_row + 64] * HH;

    // fragment constants
    const int fa_row  = (lane & 7) + ((lane >> 3) & 1) * 8;
    const int fa_koff = (lane >> 4) * 16;
    const int fb_k    = (lane & 7) + ((lane >> 3) & 1) * 8;
    const int fb_noff = (wn * 32 + (lane >> 4) * 8) * 2;

    float accg[2][4][4];
    float accu[2][4][4];
    #pragma unroll
    for (int mi = 0; mi < 2; ++mi)
        #pragma unroll
        for (int nj = 0; nj < 4; ++nj)
            #pragma unroll
            for (int qq = 0; qq < 4; ++qq) { accg[mi][nj][qq] = 0.f; accu[mi][nj][qq] = 0.f; }

    float4 bg_pre[2], bu_pre[2];

    const uint32_t a_off = a_row * 80 + a_q4 * 16;
    const int b_soff = b_krow * 144 + b_n8 * 16;

    // ---- prologue: A chunks 0,1 in flight; B chunk 0 in smem ----
    {
        cp_async16(sA + a_off,           xrow0 + a_q4 * 8);
        cp_async16(sA + a_off + 64 * 80, xrow1 + a_q4 * 8);
        CP_COMMIT();
        cp_async16(sA + 10240 + a_off,           xrow0 + 32 + a_q4 * 8);
        cp_async16(sA + 10240 + a_off + 64 * 80, xrow1 + 32 + a_q4 * 8);
        CP_COMMIT();
        size_t boff = (size_t)b_krow * FF + b_n8 * 8;
        bg_pre[0] = *reinterpret_cast<const float4*>(wg_base + boff);
        bg_pre[1] = *reinterpret_cast<const float4*>(wg_base + boff + 4);
        bu_pre[0] = *reinterpret_cast<const float4*>(wu_base + boff);
        bu_pre[1] = *reinterpret_cast<const float4*>(wu_base + boff + 4);
        uint2 lo = f4_to_h4(bg_pre[0]), hi = f4_to_h4(bg_pre[1]);
        *reinterpret_cast<uint4*>(sbuf + 30720 + b_soff) = make_uint4(lo.x, lo.y, hi.x, hi.y);
        lo = f4_to_h4(bu_pre[0]); hi = f4_to_h4(bu_pre[1]);
        *reinterpret_cast<uint4*>(sbuf + 39936 + b_soff) = make_uint4(lo.x, lo.y, hi.x, hi.y);
    }
    CP_WAIT1();
    __syncthreads();

    const int NK = HH / 32;   // 32
    int abuf = 0;             // A buffer index of current chunk
    for (int kc = 0; kc < NK; ++kc) {
        const int cur = kc & 1;
        // issue A chunk kc+2
        if (kc + 2 < NK) {
            const int k0 = (kc + 2) * 32;
            int nb = abuf + 2; if (nb >= 3) nb -= 3;
            const uint32_t Ad = sA + nb * 10240 + a_off;
            cp_async16(Ad,           xrow0 + k0 + a_q4 * 8);
            cp_async16(Ad + 64 * 80, xrow1 + k0 + a_q4 * 8);
        }
        CP_COMMIT();
        // LDG B chunk kc+1
        if (kc + 1 < NK) {
            size_t boff = (size_t)((kc + 1) * 32 + b_krow) * FF + b_n8 * 8;
            bg_pre[0] = *reinterpret_cast<const float4*>(wg_base + boff);
            bg_pre[1] = *reinterpret_cast<const float4*>(wg_base + boff + 4);
            bu_pre[0] = *reinterpret_cast<const float4*>(wu_base + boff);
            bu_pre[1] = *reinterpret_cast<const float4*>(wu_base + boff + 4);
        }

        // compute current chunk
        const uint32_t Ab  = sA + abuf * 10240;
        const uint32_t Bgb = sA + 30720 + cur * 4608;
        const uint32_t Bub = sA + 39936 + cur * 4608;
        #pragma unroll
        for (int ks = 0; ks < 2; ++ks) {
            uint32_t a[2][4];
            #pragma unroll
            for (int mi = 0; mi < 2; ++mi)
                ldm_x4(a[mi], Ab + (wm * 32 + mi * 16 + fa_row) * 80 + ks * 32 + fa_koff);
            #pragma unroll
            for (int pf = 0; pf < 2; ++pf) {
                uint32_t bg[4], bu[4];
                int boff = (ks * 16 + fb_k) * 144 + fb_noff + pf * 32;
                ldm_x4t(bg, Bgb + boff);
                ldm_x4t(bu, Bub + boff);
                #pragma unroll
                for (int mi = 0; mi < 2; ++mi) {
                    mma_f16(accg[mi][pf * 2 + 0], a[mi], bg + 0);
                    mma_f16(accg[mi][pf * 2 + 1], a[mi], bg + 2);
                    mma_f16(accu[mi][pf * 2 + 0], a[mi], bu + 0);
                    mma_f16(accu[mi][pf * 2 + 1], a[mi], bu + 2);
                }
            }
        }

        // STS B chunk kc+1
        if (kc + 1 < NK) {
            unsigned char* nbg = sbuf + 30720 + (cur ^ 1) * 4608;
            unsigned char* nbu = sbuf + 39936 + (cur ^ 1) * 4608;
            uint2 lo = f4_to_h4(bg_pre[0]), hi = f4_to_h4(bg_pre[1]);
            *reinterpret_cast<uint4*>(nbg + b_soff) = make_uint4(lo.x, lo.y, hi.x, hi.y);
            lo = f4_to_h4(bu_pre[0]); hi = f4_to_h4(bu_pre[1]);
            *reinterpret_cast<uint4*>(nbu + b_soff) = make_uint4(lo.x, lo.y, hi.x, hi.y);
        }
        CP_WAIT1();
        __syncthreads();
        if (++abuf == 3) abuf = 0;
    }

    // ---- epilogue: h = silu(g) * u -> half ----
    const int frow = lane >> 2;
    const int fcol = (lane & 3) * 2;
    #pragma unroll
    for (int mi = 0; mi < 2; ++mi) {
        #pragma unroll
        for (int nj = 0; nj < 4; ++nj) {
            int m = m0 + wm * 32 + mi * 16 + frow;
            int n = n0 + wn * 32 + nj * 8 + fcol;
            #pragma unroll
            for (int half = 0; half < 2; ++half) {
                float g0 = accg[mi][nj][half * 2 + 0];
                float g1 = accg[mi][nj][half * 2 + 1];
                float u0 = accu[mi][nj][half * 2 + 0];
                float u1 = accu[mi][nj][half * 2 + 1];
                float h0 = (g0 / (1.0f + expf(-g0))) * u0;
                float h1 = (g1 / (1.0f + expf(-g1))) * u1;
                *reinterpret_cast<__half2*>(
                    &g_hbuf[((size_t)e * CC + m + half * 8) * FF + n]) =
                    __floats2half2_rn(h0, h1);
            }
        }
    }
}

// ====================================================================
// Kernel 4: down GEMM: hbuf(half) x w_down -> obuf(half)
// CTA: M=128, N=128.  BK=32.  3-stage A pipeline, 2-stage B.
// Dyn SMEM: A 3x10240 @0; B 2x8704 @30720. total 48128.
// grid = (CC/128=8 [m fastest], HH/128=8, EE)
// ====================================================================
__global__ void __launch_bounds__(256, 2) gemm2_mma(const float* __restrict__ w_down)
{
    const int e  = blockIdx.z;
    const int m0 = blockIdx.x * 128;
    const int n0 = blockIdx.y * 128;

    int cnt = g_count[e];
    cnt = (cnt < CC) ? cnt : CC;
    if (m0 >= cnt) return;

    extern __shared__ unsigned char sbuf[];

    const int tid  = threadIdx.x;
    const int wid  = tid >> 5;
    const int lane = tid & 31;
    const int wm   = wid >> 1;
    const int wn   = wid & 1;

    const int a_row = tid >> 2;
    const int a_q4  = tid & 3;
    const int b_krow = tid >> 4;                // 0..15 (+16)
    const int b_n8   = tid & 15;

    const __half* a_base = g_hbuf + ((size_t)e * CC + m0) * FF;
    const float*  b_base = w_down + (size_t)e * FF * HH + n0;

    const uint32_t sA = smem_to_u32(sbuf);

    const int fa_row  = (lane & 7) + ((lane >> 3) & 1) * 8;
    const int fa_koff = (lane >> 4) * 16;
    const int fb_k    = (lane & 7) + ((lane >> 3) & 1) * 8;
    const int fb_noff = (wn * 64 + (lane >> 4) * 8) * 2;

    float acc[2][8][4];
    #pragma unroll
    for (int mi = 0; mi < 2; ++mi)
        #pragma unroll
        for (int nj = 0; nj < 8; ++nj)
            #pragma unroll
            for (int qq = 0; qq < 4; ++qq) acc[mi][nj][qq] = 0.f;

    float4 b_pre[4];

    const uint32_t a_off = a_row * 80 + a_q4 * 16;
    const int b_soff0 = b_krow * 272 + b_n8 * 16;
    const int b_soff1 = (b_krow + 16) * 272 + b_n8 * 16;

    // ---- prologue: A chunks 0,1; B chunk 0 ----
    {
        cp_async16(sA + a_off,           a_base + (size_t)a_row * FF + a_q4 * 8);
        cp_async16(sA + a_off + 64 * 80, a_base + (size_t)(a_row + 64) * FF + a_q4 * 8);
        CP_COMMIT();
        cp_async16(sA + 10240 + a_off,           a_base + (size_t)a_row * FF + 32 + a_q4 * 8);
        cp_async16(sA + 10240 + a_off + 64 * 80, a_base + (size_t)(a_row + 64) * FF + 32 + a_q4 * 8);
        CP_COMMIT();
        #pragma unroll
        for (int p = 0; p < 2; ++p) {
            size_t boff = (size_t)(b_krow + p * 16) * HH + b_n8 * 8;
            b_pre[p * 2 + 0] = *reinterpret_cast<const float4*>(b_base + boff);
            b_pre[p * 2 + 1] = *reinterpret_cast<const float4*>(b_base + boff + 4);
        }
        uint2 lo = f4_to_h4(b_pre[0]), hi = f4_to_h4(b_pre[1]);
        *reinterpret_cast<uint4*>(sbuf + 30720 + b_soff0) = make_uint4(lo.x, lo.y, hi.x, hi.y);
        lo = f4_to_h4(b_pre[2]); hi = f4_to_h4(b_pre[3]);
        *reinterpret_cast<uint4*>(sbuf + 30720 + b_soff1) = make_uint4(lo.x, lo.y, hi.x, hi.y);
    }
    CP_WAIT1();
    __syncthreads();

    const int NK = FF / 32;   // 16
    int abuf = 0;
    for (int kc = 0; kc < NK; ++kc) {
        const int cur = kc & 1;
        if (kc + 2 < NK) {
            const int k0 = (kc + 2) * 32;
            int nb = abuf + 2; if (nb >= 3) nb -= 3;
            const uint32_t Ad = sA + nb * 10240 + a_off;
            cp_async16(Ad,           a_base + (size_t)a_row * FF + k0 + a_q4 * 8);
            cp_async16(Ad + 64 * 80, a_base + (size_t)(a_row + 64) * FF + k0 + a_q4 * 8);
        }
        CP_COMMIT();
        if (kc + 1 < NK) {
            const int k0 = (kc + 1) * 32;
            #pragma unroll
            for (int p = 0; p < 2; ++p) {
                size_t boff = (size_t)(k0 + b_krow + p * 16) * HH + b_n8 * 8;
                b_pre[p * 2 + 0] = *reinterpret_cast<const float4*>(b_base + boff);
                b_pre[p * 2 + 1] = *reinterpret_cast<const float4*>(b_base + boff + 4);
            }
        }

        const uint32_t Ab = sA + abuf * 10240;
        const uint32_t Bb = sA + 30720 + cur * 8704;
        #pragma unroll
        for (int ks = 0; ks < 2; ++ks) {
            uint32_t a[2][4];
            #pragma unroll
            for (int mi = 0; mi < 2; ++mi)
                ldm_x4(a[mi], Ab + (wm * 32 + mi * 16 + fa_row) * 80 + ks * 32 + fa_koff);
            #pragma unroll
            for (int pf = 0; pf < 4; ++pf) {
                uint32_t b[4];
                ldm_x4t(b, Bb + (ks * 16 + fb_k) * 272 + fb_noff + pf * 32);
                #pragma unroll
                for (int mi = 0; mi < 2; ++mi) {
                    mma_f16(acc[mi][pf * 2 + 0], a[mi], b + 0);
                    mma_f16(acc[mi][pf * 2 + 1], a[mi], b + 2);
                }
            }
        }

        if (kc + 1 < NK) {
            unsigned char* nb = sbuf + 30720 + (cur ^ 1) * 8704;
            uint2 lo = f4_to_h4(b_pre[0]), hi = f4_to_h4(b_pre[1]);
            *reinterpret_cast<uint4*>(nb + b_soff0) = make_uint4(lo.x, lo.y, hi.x, hi.y);
            lo = f4_to_h4(b_pre[2]); hi = f4_to_h4(b_pre[3]);
            *reinterpret_cast<uint4*>(nb + b_soff1) = make_uint4(lo.x, lo.y, hi.x, hi.y);
        }
        CP_WAIT1();
        __syncthreads();
        if (++abuf == 3) abuf = 0;
    }

    const int frow = lane >> 2;
    const int fcol = (lane & 3) * 2;
    #pragma unroll
    for (int mi = 0; mi < 2; ++mi) {
        #pragma unroll
        for (int nj = 0; nj < 8; ++nj) {
            int m = m0 + wm * 32 + mi * 16 + frow;
            int n = n0 + wn * 64 + nj * 8 + fcol;
            #pragma unroll
            for (int half = 0; half < 2; ++half) {
                *reinterpret_cast<__half2*>(
                    &g_obuf[((size_t)e * CC + m + half * 8) * HH + n]) =
                    __floats2half2_rn(acc[mi][nj][half * 2 + 0],
                                      acc[mi][nj][half * 2 + 1]);
            }
        }
    }
}

// ====================================================================
// Kernel 5: combine — y[t] = sum_k w[t,k] * obuf[row(t,k)]  (obuf half)
// ====================================================================
__global__ void combine_kernel(float* __restrict__ y)
{
    int t = blockIdx.x;
    __shared__ int   srow[KK];
    __shared__ float sw[KK];
    if (threadIdx.x < KK) {
        int i = t * KK + threadIdx.x;
        int e = g_expert_index[i];
        int p = g_pair_pos[i];
        srow[threadIdx.x] = (p < CC) ? (e * CC + p) : -1;
        sw[threadIdx.x]   = g_weights[i];
    }
    __syncthreads();

    const int h0 = threadIdx.x * 4;     // 256 threads x 4 = 1024
    float a0 = 0.f, a1 = 0.f, a2 = 0.f, a3 = 0.f;
    #pragma unroll
    for (int k = 0; k < KK; ++k) {
        int r = srow[k];
        if (r >= 0) {
            float wk = sw[k];
            uint2 v = *reinterpret_cast<const uint2*>(&g_obuf[(size_t)r * HH + h0]);
            __half2 p0 = *reinterpret_cast<__half2*>(&v.x);
            __half2 p1 = *reinterpret_cast<__half2*>(&v.y);
            float2 f0 = __half22float2(p0);
            float2 f1 = __half22float2(p1);
            a0 += wk * f0.x; a1 += wk * f0.y;
            a2 += wk * f1.x; a3 += wk * f1.y;
        }
    }
    *reinterpret_cast<float4*>(&y[(size_t)t * HH + h0]) = make_float4(a0, a1, a2, a3);
}

// ====================================================================
extern "C" void kernel_launch(void* const* d_in, const int* in_sizes, int n_in,
                              void* d_out, int out_size)
{
    const float* x        = (const float*)d_in[0];
    const float* w_router = (const float*)d_in[1];
    const float* bias     = (const float*)d_in[2];
    const float* w_gate   = (const float*)d_in[3];
    const float* w_up     = (const float*)d_in[4];
    const float* w_down   = (const float*)d_in[5];

    float* y = (float*)d_out;
    float* logits_out = nullptr;
    float* idx_out    = nullptr;
    long long base = (long long)TT * HH;
    if ((long long)out_size >= base + (long long)TT * EE)
        logits_out = y + base;
    if ((long long)out_size >= base + (long long)TT * EE + (long long)TT * KK)
        idx_out = y + base + (long long)TT * EE;

    const int SMEM1 = 49152;
    const int SMEM2 = 48128;
    cudaFuncSetAttribute(gemm1_mma, cudaFuncAttributeMaxDynamicSharedMemorySize, SMEM1);
    cudaFuncSetAttribute(gemm2_mma, cudaFuncAttributeMaxDynamicSharedMemorySize, SMEM2);

    router_kernel<<<TT / 8, 256>>>(x, w_router, bias, logits_out, idx_out);
    pos_kernel<<<EE, 256>>>();
    gemm1_mma<<<dim3(CC / 128, FF / 64, EE), 256, SMEM1>>>(w_gate, w_up);
    gemm2_mma<<<dim3(CC / 128, HH / 128, EE), 256, SMEM2>>>(w_down);
    combine_kernel<<<TT, 256>>>(y);
}

// round 15
// speedup vs baseline: 1.2929x; 1.0154x over previous
#include <cuda_runtime.h>
#include <cuda_fp16.h>
#include <math.h>
#include <stdint.h>

// Problem constants
#define TT 4096   // tokens = B*S
#define EE 64     // experts
#define KK 8      // top_k
#define HH 1024   // hidden
#define FF 512    // expert ffn
#define CC 1024   // capacity

// -------- scratch (__device__ globals; no allocation allowed) --------
__device__ int   g_expert_index[TT * KK];
__device__ float g_weights[TT * KK];
__device__ int   g_pair_pos[TT * KK];
__device__ int   g_row_token[EE * CC];
__device__ int   g_count[EE];
__device__ alignas(16) __half g_xh[(size_t)TT * HH];         // 8 MB  (x in half)
__device__ alignas(16) __half g_hbuf[(size_t)EE * CC * FF];  // 67 MB (half)
__device__ alignas(16) __half g_obuf[(size_t)EE * CC * HH];  // 134 MB (half)

// -------- helpers --------
__device__ __forceinline__ uint32_t smem_to_u32(const void* p) {
    uint32_t a;
    asm("{ .reg .u64 t; cvta.to.shared.u64 t, %1; cvt.u32.u64 %0, t; }"
        : "=r"(a) : "l"(p));
    return a;
}
__device__ __forceinline__ uint2 f4_to_h4(float4 v) {
    __half2 a = __floats2half2_rn(v.x, v.y);
    __half2 b = __floats2half2_rn(v.z, v.w);
    uint2 r;
    r.x = *reinterpret_cast<uint32_t*>(&a);
    r.y = *reinterpret_cast<uint32_t*>(&b);
    return r;
}
__device__ __forceinline__ void ldm_x4(uint32_t* r, uint32_t addr) {
    asm volatile("ldmatrix.sync.aligned.m8n8.x4.shared.b16 {%0,%1,%2,%3}, [%4];"
        : "=r"(r[0]), "=r"(r[1]), "=r"(r[2]), "=r"(r[3]) : "r"(addr));
}
__device__ __forceinline__ void ldm_x4t(uint32_t* r, uint32_t addr) {
    asm volatile("ldmatrix.sync.aligned.m8n8.x4.trans.shared.b16 {%0,%1,%2,%3}, [%4];"
        : "=r"(r[0]), "=r"(r[1]), "=r"(r[2]), "=r"(r[3]) : "r"(addr));
}
__device__ __forceinline__ void mma_f16(float* c, const uint32_t* a, const uint32_t* b) {
    asm volatile(
        "mma.sync.aligned.m16n8k16.row.col.f32.f16.f16.f32 "
        "{%0,%1,%2,%3},{%4,%5,%6,%7},{%8,%9},{%0,%1,%2,%3};"
        : "+f"(c[0]), "+f"(c[1]), "+f"(c[2]), "+f"(c[3])
        : "r"(a[0]), "r"(a[1]), "r"(a[2]), "r"(a[3]), "r"(b[0]), "r"(b[1]));
}
__device__ __forceinline__ void cp_async16(uint32_t dst, const void* src) {
    asm volatile("cp.async.cg.shared.global [%0], [%1], 16;" :: "r"(dst), "l"(src));
}
#define CP_COMMIT() asm volatile("cp.async.commit_group;" ::: "memory")
#define CP_WAIT0()  asm volatile("cp.async.wait_group 0;" ::: "memory")
#define CP_WAIT1()  asm volatile("cp.async.wait_group 1;" ::: "memory")

// ====================================================================
// Kernel 1: router — 8 tokens/block, w_router tiled via SMEM.
// ALSO converts x -> g_xh (half) on the fly.
// ====================================================================
__global__ void __launch_bounds__(256) router_kernel(
    const float* __restrict__ x,
    const float* __restrict__ w_router,
    const float* __restrict__ bias,
    float* __restrict__ logits_out,
    float* __restrict__ idx_out)
{
    __shared__ float swT[128][65];
    __shared__ float sx[8][128];
    __shared__ float ssel[8][64];
    __shared__ float saff[8][64];

    const int tid  = threadIdx.x;
    const int warp = tid >> 5;
    const int lane = tid & 31;
    const int t0   = blockIdx.x * 8;
    const int t    = t0 + warp;

    float acc0 = 0.f, acc1 = 0.f;

    for (int hc = 0; hc < HH / 128; ++hc) {
        {
            const int e  = tid >> 2;
            const float* wr = w_router + (size_t)e * HH + hc * 128;
            #pragma unroll
            for (int p = 0; p < 8; ++p) {
                int h4 = (tid & 3) + p * 4;
                float4 v = *reinterpret_cast<const float4*>(wr + h4 * 4);
                swT[h4 * 4 + 0][e] = v.x;
                swT[h4 * 4 + 1][e] = v.y;
                swT[h4 * 4 + 2][e] = v.z;
                swT[h4 * 4 + 3][e] = v.w;
            }
        }
        {
            const int r  = tid >> 5;
            const int c4 = tid & 31;
            size_t gidx = (size_t)(t0 + r) * HH + hc * 128 + c4 * 4;
            float4 v = *reinterpret_cast<const float4*>(x + gidx);
            *reinterpret_cast<float4*>(&sx[r][c4 * 4]) = v;
            *reinterpret_cast<uint2*>(g_xh + gidx) = f4_to_h4(v);
        }
        __syncthreads();

        #pragma unroll 4
        for (int h = 0; h < 128; ++h) {
            float xv = sx[warp][h];
            acc0 += xv * swT[h][lane];
            acc1 += xv * swT[h][lane + 32];
        }
        __syncthreads();
    }

    if (logits_out) {
        logits_out[(size_t)t * EE + lane]      = acc0;
        logits_out[(size_t)t * EE + lane + 32] = acc1;
    }

    {
        float a0 = 1.0f / (1.0f + expf(-acc0));
        float a1 = 1.0f / (1.0f + expf(-acc1));
        saff[warp][lane]      = a0;
        saff[warp][lane + 32] = a1;
        ssel[warp][lane]      = a0 + bias[lane];
        ssel[warp][lane + 32] = a1 + bias[lane + 32];
    }
    __syncwarp();

    int sel_idx[KK];
    #pragma unroll
    for (int k = 0; k < KK; ++k) {
        float v  = ssel[warp][lane];      int id = lane;
        float v2 = ssel[warp][lane + 32];
        if (v2 > v) { v = v2; id = lane + 32; }
        #pragma unroll
        for (int o = 16; o; o >>= 1) {
            float ov = __shfl_xor_sync(0xffffffffu, v, o);
            int   oi = __shfl_xor_sync(0xffffffffu, id, o);
            if (ov > v || (ov == v && oi < id)) { v = ov; id = oi; }
        }
        sel_idx[k] = id;
        if (lane == 0) ssel[warp][id] = -INFINITY;
        __syncwarp();
    }

    if (lane == 0) {
        float wsum = 0.f;
        float wv[KK];
        #pragma unroll
        for (int k = 0; k < KK; ++k) { wv[k] = saff[warp][sel_idx[k]]; wsum += wv[k]; }
        #pragma unroll
        for (int k = 0; k < KK; ++k) {
            g_expert_index[t * KK + k] = sel_idx[k];
            g_weights[t * KK + k]      = wv[k] / wsum;
            if (idx_out) idx_out[(size_t)t * KK + k] = (float)sel_idx[k];
        }
    }
}

// ====================================================================
// Kernel 2: slot assignment (exact order of flattened [t,k])
// ====================================================================
__global__ void pos_kernel()
{
    int e   = blockIdx.x;
    int tid = threadIdx.x;
    const int NP    = TT * KK;
    const int chunk = NP / 256;
    __shared__ int scnt[256];

    int base = tid * chunk;
    int c = 0;
    for (int j = 0; j < chunk; ++j)
        if (g_expert_index[base + j] == e) c++;
    scnt[tid] = c;
    __syncthreads();

    if (tid == 0) {
        int run = 0;
        for (int i = 0; i < 256; ++i) { int v = scnt[i]; scnt[i] = run; run += v; }
        g_count[e] = run;
    }
    __syncthreads();

    int off = scnt[tid];
    for (int j = 0; j < chunk; ++j) {
        int i = base + j;
        if (g_expert_index[i] == e) {
            g_pair_pos[i] = off;
            if (off < CC) g_row_token[e * CC + off] = i / KK;
            off++;
        }
    }
}

// ====================================================================
// Kernel 3: gate+up GEMM + SiLU*u -> hbuf(half)  (mma.sync fp16 k16)
// CTA: M=128, N=64 (gate+up).  BK=32.  3-stage A pipe, 2-stage B.
// Dyn SMEM: A 3x10240 @0; Bg 2x4608 @30720; Bu 2x4608 @39936. 49152.
// grid = (CC/128=8 [m fastest], FF/64=8, EE)
// ====================================================================
__global__ void __launch_bounds__(256, 2) gemm1_mma(const float* __restrict__ w_gate,
                                                    const float* __restrict__ w_up)
{
    const int e  = blockIdx.z;
    const int m0 = blockIdx.x * 128;
    const int n0 = blockIdx.y * 64;

    int cnt = g_count[e];
    cnt = (cnt < CC) ? cnt : CC;
    if (m0 >= cnt) return;

    extern __shared__ unsigned char sbuf[];
    __shared__ int stok[128];

    const int tid  = threadIdx.x;
    const int wid  = tid >> 5;
    const int lane = tid & 31;
    const int wm   = wid >> 1;
    const int wn   = wid & 1;

    if (tid < 128) {
        int slot = m0 + tid;
        if (slot >= cnt) slot = cnt - 1;
        stok[tid] = g_row_token[e * CC + slot];
    }
    __syncthreads();

    const uint32_t sA = smem_to_u32(sbuf);

    const int a_row = tid >> 2;
    const int a_q4  = tid & 3;
    const int b_krow = tid >> 3;
    const int b_n8   = tid & 7;

    const float* wg_base = w_gate + (size_t)e * HH * FF + n0;
    const float* wu_base = w_up   + (size_t)e * HH * FF + n0;
    const __half* xrow0 = g_xh + (size_t)stok[a_row] * HH;
    const __half* xrow1 = g_xh + (size_t)stok[a_row + 64] * HH;

    const int fa_row  = (lane & 7) + ((lane >> 3) & 1) * 8;
    const int fa_koff = (lane >> 4) * 16;
    const int fb_k    = (lane & 7) + ((lane >> 3) & 1) * 8;
    const int fb_noff = (wn * 32 + (lane >> 4) * 8) * 2;

    float accg[2][4][4];
    float accu[2][4][4];
    #pragma unroll
    for (int mi = 0; mi < 2; ++mi)
        #pragma unroll
        for (int nj = 0; nj < 4; ++nj)
            #pragma unroll
            for (int qq = 0; qq < 4; ++qq) { accg[mi][nj][qq] = 0.f; accu[mi][nj][qq] = 0.f; }

    float4 bg_pre[2], bu_pre[2];

    const uint32_t a_off = a_row * 80 + a_q4 * 16;
    const int b_soff = b_krow * 144 + b_n8 * 16;

    // prologue: A chunks 0,1 in flight; B chunk 0 in smem
    {
        cp_async16(sA + a_off,           xrow0 + a_q4 * 8);
        cp_async16(sA + a_off + 64 * 80, xrow1 + a_q4 * 8);
        CP_COMMIT();
        cp_async16(sA + 10240 + a_off,           xrow0 + 32 + a_q4 * 8);
        cp_async16(sA + 10240 + a_off + 64 * 80, xrow1 + 32 + a_q4 * 8);
        CP_COMMIT();
        size_t boff = (size_t)b_krow * FF + b_n8 * 8;
        bg_pre[0] = *reinterpret_cast<const float4*>(wg_base + boff);
        bg_pre[1] = *reinterpret_cast<const float4*>(wg_base + boff + 4);
        bu_pre[0] = *reinterpret_cast<const float4*>(wu_base + boff);
        bu_pre[1] = *reinterpret_cast<const float4*>(wu_base + boff + 4);
        uint2 lo = f4_to_h4(bg_pre[0]), hi = f4_to_h4(bg_pre[1]);
        *reinterpret_cast<uint4*>(sbuf + 30720 + b_soff) = make_uint4(lo.x, lo.y, hi.x, hi.y);
        lo = f4_to_h4(bu_pre[0]); hi = f4_to_h4(bu_pre[1]);
        *reinterpret_cast<uint4*>(sbuf + 39936 + b_soff) = make_uint4(lo.x, lo.y, hi.x, hi.y);
    }
    CP_WAIT1();
    __syncthreads();

    const int NK = HH / 32;   // 32
    int abuf = 0;
    for (int kc = 0; kc < NK; ++kc) {
        const int cur = kc & 1;
        if (kc + 2 < NK) {
            const int k0 = (kc + 2) * 32;
            int nb = abuf + 2; if (nb >= 3) nb -= 3;
            const uint32_t Ad = sA + nb * 10240 + a_off;
            cp_async16(Ad,           xrow0 + k0 + a_q4 * 8);
            cp_async16(Ad + 64 * 80, xrow1 + k0 + a_q4 * 8);
        }
        CP_COMMIT();
        if (kc + 1 < NK) {
            size_t boff = (size_t)((kc + 1) * 32 + b_krow) * FF + b_n8 * 8;
            bg_pre[0] = *reinterpret_cast<const float4*>(wg_base + boff);
            bg_pre[1] = *reinterpret_cast<const float4*>(wg_base + boff + 4);
            bu_pre[0] = *reinterpret_cast<const float4*>(wu_base + boff);
            bu_pre[1] = *reinterpret_cast<const float4*>(wu_base + boff + 4);
        }

        const uint32_t Ab  = sA + abuf * 10240;
        const uint32_t Bgb = sA + 30720 + cur * 4608;
        const uint32_t Bub = sA + 39936 + cur * 4608;
        #pragma unroll
        for (int ks = 0; ks < 2; ++ks) {
            uint32_t a[2][4];
            #pragma unroll
            for (int mi = 0; mi < 2; ++mi)
                ldm_x4(a[mi], Ab + (wm * 32 + mi * 16 + fa_row) * 80 + ks * 32 + fa_koff);
            #pragma unroll
            for (int pf = 0; pf < 2; ++pf) {
                uint32_t bg[4], bu[4];
                int boff = (ks * 16 + fb_k) * 144 + fb_noff + pf * 32;
                ldm_x4t(bg, Bgb + boff);
                ldm_x4t(bu, Bub + boff);
                #pragma unroll
                for (int mi = 0; mi < 2; ++mi) {
                    mma_f16(accg[mi][pf * 2 + 0], a[mi], bg + 0);
                    mma_f16(accg[mi][pf * 2 + 1], a[mi], bg + 2);
                    mma_f16(accu[mi][pf * 2 + 0], a[mi], bu + 0);
                    mma_f16(accu[mi][pf * 2 + 1], a[mi], bu + 2);
                }
            }
        }

        if (kc + 1 < NK) {
            unsigned char* nbg = sbuf + 30720 + (cur ^ 1) * 4608;
            unsigned char* nbu = sbuf + 39936 + (cur ^ 1) * 4608;
            uint2 lo = f4_to_h4(bg_pre[0]), hi = f4_to_h4(bg_pre[1]);
            *reinterpret_cast<uint4*>(nbg + b_soff) = make_uint4(lo.x, lo.y, hi.x, hi.y);
            lo = f4_to_h4(bu_pre[0]); hi = f4_to_h4(bu_pre[1]);
            *reinterpret_cast<uint4*>(nbu + b_soff) = make_uint4(lo.x, lo.y, hi.x, hi.y);
        }
        CP_WAIT1();
        __syncthreads();
        if (++abuf == 3) abuf = 0;
    }

    // epilogue: h = silu(g) * u -> half
    const int frow = lane >> 2;
    const int fcol = (lane & 3) * 2;
    #pragma unroll
    for (int mi = 0; mi < 2; ++mi) {
        #pragma unroll
        for (int nj = 0; nj < 4; ++nj) {
            int m = m0 + wm * 32 + mi * 16 + frow;
            int n = n0 + wn * 32 + nj * 8 + fcol;
            #pragma unroll
            for (int half = 0; half < 2; ++half) {
                float g0 = accg[mi][nj][half * 2 + 0];
                float g1 = accg[mi][nj][half * 2 + 1];
                float u0 = accu[mi][nj][half * 2 + 0];
                float u1 = accu[mi][nj][half * 2 + 1];
                float h0 = (g0 / (1.0f + expf(-g0))) * u0;
                float h1 = (g1 / (1.0f + expf(-g1))) * u1;
                *reinterpret_cast<__half2*>(
                    &g_hbuf[((size_t)e * CC + m + half * 8) * FF + n]) =
                    __floats2half2_rn(h0, h1);
            }
        }
    }
}

// ====================================================================
// Kernel 4: down GEMM: hbuf(half) x w_down -> obuf(half)
// CTA: M=128, N=128.  BK=32, 2-stage double buffer (round-13 structure).
// A tile: [128][32 halves] stride 80B.  B tile: [32 k][128 n] stride 272B.
// Static SMEM: A0=0(10240) A1=10240, B0=20480(8704) B1=29184; 37888.
// grid = (CC/128=8 [m fastest], HH/128=8, EE)
// ====================================================================
__global__ void __launch_bounds__(256, 2) gemm2_mma(const float* __restrict__ w_down)
{
    const int e  = blockIdx.z;
    const int m0 = blockIdx.x * 128;
    const int n0 = blockIdx.y * 128;

    int cnt = g_count[e];
    cnt = (cnt < CC) ? cnt : CC;
    if (m0 >= cnt) return;

    __shared__ alignas(16) unsigned char sbuf[37888];

    const int tid  = threadIdx.x;
    const int wid  = tid >> 5;
    const int lane = tid & 31;
    const int wm   = wid >> 1;
    const int wn   = wid & 1;

    const int a_row = tid >> 2;
    const int a_q4  = tid & 3;
    const int b_krow = tid >> 4;
    const int b_n8   = tid & 15;

    const __half* a_base = g_hbuf + ((size_t)e * CC + m0) * FF;
    const float*  b_base = w_down + (size_t)e * FF * HH + n0;

    const uint32_t sA = smem_to_u32(sbuf);

    const int fa_row  = (lane & 7) + ((lane >> 3) & 1) * 8;
    const int fa_koff = (lane >> 4) * 16;
    const int fb_k    = (lane & 7) + ((lane >> 3) & 1) * 8;
    const int fb_noff = (wn * 64 + (lane >> 4) * 8) * 2;

    float acc[2][8][4];
    #pragma unroll
    for (int mi = 0; mi < 2; ++mi)
        #pragma unroll
        for (int nj = 0; nj < 8; ++nj)
            #pragma unroll
            for (int qq = 0; qq < 4; ++qq) acc[mi][nj][qq] = 0.f;

    float4 b_pre[4];

    // prologue chunk 0
    {
        const uint32_t Ad = sA + a_row * 80 + a_q4 * 16;
        cp_async16(Ad,           a_base + (size_t)a_row * FF + a_q4 * 8);
        cp_async16(Ad + 64 * 80, a_base + (size_t)(a_row + 64) * FF + a_q4 * 8);
        CP_COMMIT();
        #pragma unroll
        for (int p = 0; p < 2; ++p) {
            size_t boff = (size_t)(b_krow + p * 16) * HH + b_n8 * 8;
            b_pre[p * 2 + 0] = *reinterpret_cast<const float4*>(b_base + boff);
            b_pre[p * 2 + 1] = *reinterpret_cast<const float4*>(b_base + boff + 4);
        }
        #pragma unroll
        for (int p = 0; p < 2; ++p) {
            int off = (b_krow + p * 16) * 272 + b_n8 * 16;
            uint2 lo = f4_to_h4(b_pre[p * 2 + 0]), hi = f4_to_h4(b_pre[p * 2 + 1]);
            *reinterpret_cast<uint4*>(sbuf + 20480 + off) = make_uint4(lo.x, lo.y, hi.x, hi.y);
        }
    }
    CP_WAIT0();
    __syncthreads();

    const int NK = FF / 32;   // 16
    for (int kc = 0; kc < NK; ++kc) {
        const int cur = kc & 1;
        const int has_next = (kc + 1 < NK);
        if (has_next) {
            const int k0 = (kc + 1) * 32;
            const uint32_t Ad = sA + (cur ^ 1) * 10240 + a_row * 80 + a_q4 * 16;
            cp_async16(Ad,           a_base + (size_t)a_row * FF + k0 + a_q4 * 8);
            cp_async16(Ad + 64 * 80, a_base + (size_t)(a_row + 64) * FF + k0 + a_q4 * 8);
            CP_COMMIT();
            #pragma unroll
            for (int p = 0; p < 2; ++p) {
                size_t boff = (size_t)(k0 + b_krow + p * 16) * HH + b_n8 * 8;
                b_pre[p * 2 + 0] = *reinterpret_cast<const float4*>(b_base + boff);
                b_pre[p * 2 + 1] = *reinterpret_cast<const float4*>(b_base + boff + 4);
            }
        }

        const uint32_t Ab = sA + cur * 10240;
        const uint32_t Bb = sA + 20480 + cur * 8704;
        #pragma unroll
        for (int ks = 0; ks < 2; ++ks) {
            uint32_t a[2][4];
            #pragma unroll
            for (int mi = 0; mi < 2; ++mi)
                ldm_x4(a[mi], Ab + (wm * 32 + mi * 16 + fa_row) * 80 + ks * 32 + fa_koff);
            #pragma unroll
            for (int pf = 0; pf < 4; ++pf) {
                uint32_t b[4];
                ldm_x4t(b, Bb + (ks * 16 + fb_k) * 272 + fb_noff + pf * 32);
                #pragma unroll
                for (int mi = 0; mi < 2; ++mi) {
                    mma_f16(acc[mi][pf * 2 + 0], a[mi], b + 0);
                    mma_f16(acc[mi][pf * 2 + 1], a[mi], b + 2);
                }
            }
        }

        if (has_next) {
            unsigned char* nb = sbuf + 20480 + (cur ^ 1) * 8704;
            #pragma unroll
            for (int p = 0; p < 2; ++p) {
                int off = (b_krow + p * 16) * 272 + b_n8 * 16;
                uint2 lo = f4_to_h4(b_pre[p * 2 + 0]), hi = f4_to_h4(b_pre[p * 2 + 1]);
                *reinterpret_cast<uint4*>(nb + off) = make_uint4(lo.x, lo.y, hi.x, hi.y);
            }
        }
        CP_WAIT0();
        __syncthreads();
    }

    const int frow = lane >> 2;
    const int fcol = (lane & 3) * 2;
    #pragma unroll
    for (int mi = 0; mi < 2; ++mi) {
        #pragma unroll
        for (int nj = 0; nj < 8; ++nj) {
            int m = m0 + wm * 32 + mi * 16 + frow;
            int n = n0 + wn * 64 + nj * 8 + fcol;
            #pragma unroll
            for (int half = 0; half < 2; ++half) {
                *reinterpret_cast<__half2*>(
                    &g_obuf[((size_t)e * CC + m + half * 8) * HH + n]) =
                    __floats2half2_rn(acc[mi][nj][half * 2 + 0],
                                      acc[mi][nj][half * 2 + 1]);
            }
        }
    }
}

// ====================================================================
// Kernel 5: combine — y[t] = sum_k w[t,k] * obuf[row(t,k)]
// 128 threads x 8 halves (uint4 loads).
// ====================================================================
__global__ void __launch_bounds__(128) combine_kernel(float* __restrict__ y)
{
    int t = blockIdx.x;
    __shared__ int   srow[KK];
    __shared__ float sw[KK];
    if (threadIdx.x < KK) {
        int i = t * KK + threadIdx.x;
        int e = g_expert_index[i];
        int p = g_pair_pos[i];
        srow[threadIdx.x] = (p < CC) ? (e * CC + p) : -1;
        sw[threadIdx.x]   = g_weights[i];
    }
    __syncthreads();

    const int h0 = threadIdx.x * 8;     // 128 threads x 8 = 1024
    float a[8];
    #pragma unroll
    for (int q = 0; q < 8; ++q) a[q] = 0.f;
    #pragma unroll
    for (int k = 0; k < KK; ++k) {
        int r = srow[k];
        if (r >= 0) {
            float wk = sw[k];
            uint4 v = *reinterpret_cast<const uint4*>(&g_obuf[(size_t)r * HH + h0]);
            const __half2* hp = reinterpret_cast<const __half2*>(&v);
            #pragma unroll
            for (int q = 0; q < 4; ++q) {
                float2 f = __half22float2(hp[q]);
                a[q * 2 + 0] += wk * f.x;
                a[q * 2 + 1] += wk * f.y;
            }
        }
    }
    float4* yp = reinterpret_cast<float4*>(&y[(size_t)t * HH + h0]);
    yp[0] = make_float4(a[0], a[1], a[2], a[3]);
    yp[1] = make_float4(a[4], a[5], a[6], a[7]);
}

// ====================================================================
extern "C" void kernel_launch(void* const* d_in, const int* in_sizes, int n_in,
                              void* d_out, int out_size)
{
    const float* x        = (const float*)d_in[0];
    const float* w_router = (const float*)d_in[1];
    const float* bias     = (const float*)d_in[2];
    const float* w_gate   = (const float*)d_in[3];
    const float* w_up     = (const float*)d_in[4];
    const float* w_down   = (const float*)d_in[5];

    float* y = (float*)d_out;
    float* logits_out = nullptr;
    float* idx_out    = nullptr;
    long long base = (long long)TT * HH;
    if ((long long)out_size >= base + (long long)TT * EE)
        logits_out = y + base;
    if ((long long)out_size >= base + (long long)TT * EE + (long long)TT * KK)
        idx_out = y + base + (long long)TT * EE;

    const int SMEM1 = 49152;
    cudaFuncSetAttribute(gemm1_mma, cudaFuncAttributeMaxDynamicSharedMemorySize, SMEM1);

    router_kernel<<<TT / 8, 256>>>(x, w_router, bias, logits_out, idx_out);
    pos_kernel<<<EE, 256>>>();
    gemm1_mma<<<dim3(CC / 128, FF / 64, EE), 256, SMEM1>>>(w_gate, w_up);
    gemm2_mma<<<dim3(CC / 128, HH / 128, EE), 256>>>(w_down);
    combine_kernel<<<TT, 128>>>(y);
}

// round 16
// speedup vs baseline: 1.3583x; 1.0505x over previous
#include <cuda_runtime.h>
#include <cuda_fp16.h>
#include <math.h>
#include <stdint.h>

// Problem constants
#define TT 4096   // tokens = B*S
#define EE 64     // experts
#define KK 8      // top_k
#define HH 1024   // hidden
#define FF 512    // expert ffn
#define CC 1024   // capacity

// -------- scratch (__device__ globals; no allocation allowed) --------
__device__ int   g_expert_index[TT * KK];
__device__ float g_weights[TT * KK];
__device__ int   g_pair_pos[TT * KK];
__device__ int   g_row_token[EE * CC];
__device__ int   g_count[EE];
__device__ alignas(16) __half g_xh[(size_t)TT * HH];         // 8 MB  (x in half)
__device__ alignas(16) __half g_hbuf[(size_t)EE * CC * FF];  // 67 MB (half)
__device__ alignas(16) __half g_obuf[(size_t)EE * CC * HH];  // 134 MB (half)

// -------- helpers --------
__device__ __forceinline__ uint32_t smem_to_u32(const void* p) {
    uint32_t a;
    asm("{ .reg .u64 t; cvta.to.shared.u64 t, %1; cvt.u32.u64 %0, t; }"
        : "=r"(a) : "l"(p));
    return a;
}
__device__ __forceinline__ uint2 f4_to_h4(float4 v) {
    __half2 a = __floats2half2_rn(v.x, v.y);
    __half2 b = __floats2half2_rn(v.z, v.w);
    uint2 r;
    r.x = *reinterpret_cast<uint32_t*>(&a);
    r.y = *reinterpret_cast<uint32_t*>(&b);
    return r;
}
__device__ __forceinline__ void ldm_x4(uint32_t* r, uint32_t addr) {
    asm volatile("ldmatrix.sync.aligned.m8n8.x4.shared.b16 {%0,%1,%2,%3}, [%4];"
        : "=r"(r[0]), "=r"(r[1]), "=r"(r[2]), "=r"(r[3]) : "r"(addr));
}
__device__ __forceinline__ void ldm_x4t(uint32_t* r, uint32_t addr) {
    asm volatile("ldmatrix.sync.aligned.m8n8.x4.trans.shared.b16 {%0,%1,%2,%3}, [%4];"
        : "=r"(r[0]), "=r"(r[1]), "=r"(r[2]), "=r"(r[3]) : "r"(addr));
}
__device__ __forceinline__ void mma_f16(float* c, const uint32_t* a, const uint32_t* b) {
    asm volatile(
        "mma.sync.aligned.m16n8k16.row.col.f32.f16.f16.f32 "
        "{%0,%1,%2,%3},{%4,%5,%6,%7},{%8,%9},{%0,%1,%2,%3};"
        : "+f"(c[0]), "+f"(c[1]), "+f"(c[2]), "+f"(c[3])
        : "r"(a[0]), "r"(a[1]), "r"(a[2]), "r"(a[3]), "r"(b[0]), "r"(b[1]));
}
__device__ __forceinline__ void cp_async16(uint32_t dst, const void* src) {
    asm volatile("cp.async.cg.shared.global [%0], [%1], 16;" :: "r"(dst), "l"(src));
}
#define CP_COMMIT() asm volatile("cp.async.commit_group;" ::: "memory")
#define CP_WAIT0()  asm volatile("cp.async.wait_group 0;" ::: "memory")
#define CP_WAIT1()  asm volatile("cp.async.wait_group 1;" ::: "memory")

// ====================================================================
// Kernel 1: router — 16 tokens/block (2 per warp), w_router tiled.
// Also converts x -> g_xh (half) on the fly.
// ====================================================================
__global__ void __launch_bounds__(256) router_kernel(
    const float* __restrict__ x,
    const float* __restrict__ w_router,
    const float* __restrict__ bias,
    float* __restrict__ logits_out,
    float* __restrict__ idx_out)
{
    __shared__ float swT[128][65];   // 33280 B
    __shared__ float sx[16][128];    // 8192 B
    __shared__ float ssel[16][64];   // 4096 B

    const int tid  = threadIdx.x;
    const int warp = tid >> 5;
    const int lane = tid & 31;
    const int t0   = blockIdx.x * 16;

    float acc0a = 0.f, acc1a = 0.f;  // token t0 + warp*2
    float acc0b = 0.f, acc1b = 0.f;  // token t0 + warp*2 + 1

    for (int hc = 0; hc < HH / 128; ++hc) {
        // w_router chunk transposed into swT[h][e]
        {
            const int e  = tid >> 2;
            const float* wr = w_router + (size_t)e * HH + hc * 128;
            #pragma unroll
            for (int p = 0; p < 8; ++p) {
                int h4 = (tid & 3) + p * 4;
                float4 v = *reinterpret_cast<const float4*>(wr + h4 * 4);
                swT[h4 * 4 + 0][e] = v.x;
                swT[h4 * 4 + 1][e] = v.y;
                swT[h4 * 4 + 2][e] = v.z;
                swT[h4 * 4 + 3][e] = v.w;
            }
        }
        // 16 token rows' h-chunk, fused fp32->half store to g_xh
        {
            const int r  = tid >> 4;         // 0..15
            const int c4 = tid & 15;         // 0..15
            #pragma unroll
            for (int p = 0; p < 2; ++p) {
                int col4 = c4 + p * 16;      // 0..31
                size_t gidx = (size_t)(t0 + r) * HH + hc * 128 + col4 * 4;
                float4 v = *reinterpret_cast<const float4*>(x + gidx);
                *reinterpret_cast<float4*>(&sx[r][col4 * 4]) = v;
                *reinterpret_cast<uint2*>(g_xh + gidx) = f4_to_h4(v);
            }
        }
        __syncthreads();

        const float* sxa = sx[warp * 2];
        const float* sxb = sx[warp * 2 + 1];
        #pragma unroll 4
        for (int h = 0; h < 128; ++h) {
            float w0 = swT[h][lane];
            float w1 = swT[h][lane + 32];
            float xa = sxa[h];
            float xb = sxb[h];
            acc0a += xa * w0; acc1a += xa * w1;
            acc0b += xb * w0; acc1b += xb * w1;
        }
        __syncthreads();
    }

    #pragma unroll
    for (int tt = 0; tt < 2; ++tt) {
        const int t = t0 + warp * 2 + tt;
        const int srow = warp * 2 + tt;
        float acc0 = tt ? acc0b : acc0a;
        float acc1 = tt ? acc1b : acc1a;

        if (logits_out) {
            logits_out[(size_t)t * EE + lane]      = acc0;
            logits_out[(size_t)t * EE + lane + 32] = acc1;
        }

        float a0 = 1.0f / (1.0f + expf(-acc0));
        float a1 = 1.0f / (1.0f + expf(-acc1));
        ssel[srow][lane]      = a0 + bias[lane];
        ssel[srow][lane + 32] = a1 + bias[lane + 32];
        __syncwarp();

        int   sel_idx[KK];
        float sel_val[KK];
        #pragma unroll
        for (int k = 0; k < KK; ++k) {
            float v  = ssel[srow][lane];      int id = lane;
            float v2 = ssel[srow][lane + 32];
            if (v2 > v) { v = v2; id = lane + 32; }
            #pragma unroll
            for (int o = 16; o; o >>= 1) {
                float ov = __shfl_xor_sync(0xffffffffu, v, o);
                int   oi = __shfl_xor_sync(0xffffffffu, id, o);
                if (ov > v || (ov == v && oi < id)) { v = ov; id = oi; }
            }
            sel_idx[k] = id;
            sel_val[k] = v;
            if (lane == 0) ssel[srow][id] = -INFINITY;
            __syncwarp();
        }

        if (lane == 0) {
            float wsum = 0.f;
            float wv[KK];
            #pragma unroll
            for (int k = 0; k < KK; ++k) {
                wv[k] = sel_val[k] - bias[sel_idx[k]];   // affinity = sel - bias
                wsum += wv[k];
            }
            #pragma unroll
            for (int k = 0; k < KK; ++k) {
                g_expert_index[t * KK + k] = sel_idx[k];
                g_weights[t * KK + k]      = wv[k] / wsum;
                if (idx_out) idx_out[(size_t)t * KK + k] = (float)sel_idx[k];
            }
        }
    }
}

// ====================================================================
// Kernel 2: slot assignment (exact order of flattened [t,k])
// warp-scan prefix instead of serial thread-0 loop.
// ====================================================================
__global__ void pos_kernel()
{
    int e    = blockIdx.x;
    int tid  = threadIdx.x;
    int wid  = tid >> 5;
    int lane = tid & 31;
    const int NP    = TT * KK;
    const int chunk = NP / 256;
    __shared__ int wsum[8];

    int base = tid * chunk;
    int c = 0;
    for (int j = 0; j < chunk; ++j)
        if (g_expert_index[base + j] == e) c++;

    // inclusive warp scan
    int v = c;
    #pragma unroll
    for (int o = 1; o < 32; o <<= 1) {
        int n = __shfl_up_sync(0xffffffffu, v, o);
        if (lane >= o) v += n;
    }
    if (lane == 31) wsum[wid] = v;
    __syncthreads();
    if (wid == 0 && lane < 8) {
        int s = wsum[lane];
        #pragma unroll
        for (int o = 1; o < 8; o <<= 1) {
            int n = __shfl_up_sync(0xffu, s, o);
            if (lane >= o) s += n;
        }
        wsum[lane] = s;
    }
    __syncthreads();

    int off = v - c + (wid ? wsum[wid - 1] : 0);   // exclusive prefix
    if (tid == 255) g_count[e] = off + c;

    for (int j = 0; j < chunk; ++j) {
        int i = base + j;
        if (g_expert_index[i] == e) {
            g_pair_pos[i] = off;
            if (off < CC) g_row_token[e * CC + off] = i / KK;
            off++;
        }
    }
}

// ====================================================================
// Kernel 3: gate+up GEMM + SiLU*u -> hbuf(half)  (mma.sync fp16 k16)
// CTA: M=128, N=64 (gate+up).  BK=32.  3-stage A pipe, 2-stage B.
// Dyn SMEM: A 3x10240 @0; Bg 2x4608 @30720; Bu 2x4608 @39936. 49152.
// grid = (CC/128=8 [m fastest], FF/64=8, EE)
// ====================================================================
__global__ void __launch_bounds__(256, 2) gemm1_mma(const float* __restrict__ w_gate,
                                                    const float* __restrict__ w_up)
{
    const int e  = blockIdx.z;
    const int m0 = blockIdx.x * 128;
    const int n0 = blockIdx.y * 64;

    int cnt = g_count[e];
    cnt = (cnt < CC) ? cnt : CC;
    if (m0 >= cnt) return;

    extern __shared__ unsigned char sbuf[];
    __shared__ int stok[128];

    const int tid  = threadIdx.x;
    const int wid  = tid >> 5;
    const int lane = tid & 31;
    const int wm   = wid >> 1;
    const int wn   = wid & 1;

    if (tid < 128) {
        int slot = m0 + tid;
        if (slot >= cnt) slot = cnt - 1;
        stok[tid] = g_row_token[e * CC + slot];
    }
    __syncthreads();

    const uint32_t sA = smem_to_u32(sbuf);

    const int a_row = tid >> 2;
    const int a_q4  = tid & 3;
    const int b_krow = tid >> 3;
    const int b_n8   = tid & 7;

    const float* wg_base = w_gate + (size_t)e * HH * FF + n0;
    const float* wu_base = w_up   + (size_t)e * HH * FF + n0;
    const __half* xrow0 = g_xh + (size_t)stok[a_row] * HH;
    const __half* xrow1 = g_xh + (size_t)stok[a_row + 64] * HH;

    const int fa_row  = (lane & 7) + ((lane >> 3) & 1) * 8;
    const int fa_koff = (lane >> 4) * 16;
    const int fb_k    = (lane & 7) + ((lane >> 3) & 1) * 8;
    const int fb_noff = (wn * 32 + (lane >> 4) * 8) * 2;

    float accg[2][4][4];
    float accu[2][4][4];
    #pragma unroll
    for (int mi = 0; mi < 2; ++mi)
        #pragma unroll
        for (int nj = 0; nj < 4; ++nj)
            #pragma unroll
            for (int qq = 0; qq < 4; ++qq) { accg[mi][nj][qq] = 0.f; accu[mi][nj][qq] = 0.f; }

    float4 bg_pre[2], bu_pre[2];

    const uint32_t a_off = a_row * 80 + a_q4 * 16;
    const int b_soff = b_krow * 144 + b_n8 * 16;

    // prologue: A chunks 0,1 in flight; B chunk 0 in smem
    {
        cp_async16(sA + a_off,           xrow0 + a_q4 * 8);
        cp_async16(sA + a_off + 64 * 80, xrow1 + a_q4 * 8);
        CP_COMMIT();
        cp_async16(sA + 10240 + a_off,           xrow0 + 32 + a_q4 * 8);
        cp_async16(sA + 10240 + a_off + 64 * 80, xrow1 + 32 + a_q4 * 8);
        CP_COMMIT();
        size_t boff = (size_t)b_krow * FF + b_n8 * 8;
        bg_pre[0] = *reinterpret_cast<const float4*>(wg_base + boff);
        bg_pre[1] = *reinterpret_cast<const float4*>(wg_base + boff + 4);
        bu_pre[0] = *reinterpret_cast<const float4*>(wu_base + boff);
        bu_pre[1] = *reinterpret_cast<const float4*>(wu_base + boff + 4);
        uint2 lo = f4_to_h4(bg_pre[0]), hi = f4_to_h4(bg_pre[1]);
        *reinterpret_cast<uint4*>(sbuf + 30720 + b_soff) = make_uint4(lo.x, lo.y, hi.x, hi.y);
        lo = f4_to_h4(bu_pre[0]); hi = f4_to_h4(bu_pre[1]);
        *reinterpret_cast<uint4*>(sbuf + 39936 + b_soff) = make_uint4(lo.x, lo.y, hi.x, hi.y);
    }
    CP_WAIT1();
    __syncthreads();

    const int NK = HH / 32;   // 32
    int abuf = 0;
    for (int kc = 0; kc < NK; ++kc) {
        const int cur = kc & 1;
        if (kc + 2 < NK) {
            const int k0 = (kc + 2) * 32;
            int nb = abuf + 2; if (nb >= 3) nb -= 3;
            const uint32_t Ad = sA + nb * 10240 + a_off;
            cp_async16(Ad,           xrow0 + k0 + a_q4 * 8);
            cp_async16(Ad + 64 * 80, xrow1 + k0 + a_q4 * 8);
        }
        CP_COMMIT();
        if (kc + 1 < NK) {
            size_t boff = (size_t)((kc + 1) * 32 + b_krow) * FF + b_n8 * 8;
            bg_pre[0] = *reinterpret_cast<const float4*>(wg_base + boff);
            bg_pre[1] = *reinterpret_cast<const float4*>(wg_base + boff + 4);
            bu_pre[0] = *reinterpret_cast<const float4*>(wu_base + boff);
            bu_pre[1] = *reinterpret_cast<const float4*>(wu_base + boff + 4);
        }

        const uint32_t Ab  = sA + abuf * 10240;
        const uint32_t Bgb = sA + 30720 + cur * 4608;
        const uint32_t Bub = sA + 39936 + cur * 4608;
        #pragma unroll
        for (int ks = 0; ks < 2; ++ks) {
            uint32_t a[2][4];
            #pragma unroll
            for (int mi = 0; mi < 2; ++mi)
                ldm_x4(a[mi], Ab + (wm * 32 + mi * 16 + fa_row) * 80 + ks * 32 + fa_koff);
            #pragma unroll
            for (int pf = 0; pf < 2; ++pf) {
                uint32_t bg[4], bu[4];
                int boff = (ks * 16 + fb_k) * 144 + fb_noff + pf * 32;
                ldm_x4t(bg, Bgb + boff);
                ldm_x4t(bu, Bub + boff);
                #pragma unroll
                for (int mi = 0; mi < 2; ++mi) {
                    mma_f16(accg[mi][pf * 2 + 0], a[mi], bg + 0);
                    mma_f16(accg[mi][pf * 2 + 1], a[mi], bg + 2);
                    mma_f16(accu[mi][pf * 2 + 0], a[mi], bu + 0);
                    mma_f16(accu[mi][pf * 2 + 1], a[mi], bu + 2);
                }
            }
        }

        if (kc + 1 < NK) {
            unsigned char* nbg = sbuf + 30720 + (cur ^ 1) * 4608;
            unsigned char* nbu = sbuf + 39936 + (cur ^ 1) * 4608;
            uint2 lo = f4_to_h4(bg_pre[0]), hi = f4_to_h4(bg_pre[1]);
            *reinterpret_cast<uint4*>(nbg + b_soff) = make_uint4(lo.x, lo.y, hi.x, hi.y);
            lo = f4_to_h4(bu_pre[0]); hi = f4_to_h4(bu_pre[1]);
            *reinterpret_cast<uint4*>(nbu + b_soff) = make_uint4(lo.x, lo.y, hi.x, hi.y);
        }
        CP_WAIT1();
        __syncthreads();
        if (++abuf == 3) abuf = 0;
    }

    const int frow = lane >> 2;
    const int fcol = (lane & 3) * 2;
    #pragma unroll
    for (int mi = 0; mi < 2; ++mi) {
        #pragma unroll
        for (int nj = 0; nj < 4; ++nj) {
            int m = m0 + wm * 32 + mi * 16 + frow;
            int n = n0 + wn * 32 + nj * 8 + fcol;
            #pragma unroll
            for (int half = 0; half < 2; ++half) {
                float g0 = accg[mi][nj][half * 2 + 0];
                float g1 = accg[mi][nj][half * 2 + 1];
                float u0 = accu[mi][nj][half * 2 + 0];
                float u1 = accu[mi][nj][half * 2 + 1];
                float h0 = (g0 / (1.0f + expf(-g0))) * u0;
                float h1 = (g1 / (1.0f + expf(-g1))) * u1;
                *reinterpret_cast<__half2*>(
                    &g_hbuf[((size_t)e * CC + m + half * 8) * FF + n]) =
                    __floats2half2_rn(h0, h1);
            }
        }
    }
}

// ====================================================================
// Kernel 4: down GEMM: hbuf(half) x w_down -> obuf(half)
// CTA: M=128, N=128.  BK=32, 2-stage double buffer.
// Static SMEM: A0=0(10240) A1=10240, B0=20480(8704) B1=29184; 37888.
// grid = (CC/128=8 [m fastest], HH/128=8, EE)
// ====================================================================
__global__ void __launch_bounds__(256, 2) gemm2_mma(const float* __restrict__ w_down)
{
    const int e  = blockIdx.z;
    const int m0 = blockIdx.x * 128;
    const int n0 = blockIdx.y * 128;

    int cnt = g_count[e];
    cnt = (cnt < CC) ? cnt : CC;
    if (m0 >= cnt) return;

    __shared__ alignas(16) unsigned char sbuf[37888];

    const int tid  = threadIdx.x;
    const int wid  = tid >> 5;
    const int lane = tid & 31;
    const int wm   = wid >> 1;
    const int wn   = wid & 1;

    const int a_row = tid >> 2;
    const int a_q4  = tid & 3;
    const int b_krow = tid >> 4;
    const int b_n8   = tid & 15;

    const __half* a_base = g_hbuf + ((size_t)e * CC + m0) * FF;
    const float*  b_base = w_down + (size_t)e * FF * HH + n0;

    const uint32_t sA = smem_to_u32(sbuf);

    const int fa_row  = (lane & 7) + ((lane >> 3) & 1) * 8;
    const int fa_koff = (lane >> 4) * 16;
    const int fb_k    = (lane & 7) + ((lane >> 3) & 1) * 8;
    const int fb_noff = (wn * 64 + (lane >> 4) * 8) * 2;

    float acc[2][8][4];
    #pragma unroll
    for (int mi = 0; mi < 2; ++mi)
        #pragma unroll
        for (int nj = 0; nj < 8; ++nj)
            #pragma unroll
            for (int qq = 0; qq < 4; ++qq) acc[mi][nj][qq] = 0.f;

    float4 b_pre[4];

    // prologue chunk 0
    {
        const uint32_t Ad = sA + a_row * 80 + a_q4 * 16;
        cp_async16(Ad,           a_base + (size_t)a_row * FF + a_q4 * 8);
        cp_async16(Ad + 64 * 80, a_base + (size_t)(a_row + 64) * FF + a_q4 * 8);
        CP_COMMIT();
        #pragma unroll
        for (int p = 0; p < 2; ++p) {
            size_t boff = (size_t)(b_krow + p * 16) * HH + b_n8 * 8;
            b_pre[p * 2 + 0] = *reinterpret_cast<const float4*>(b_base + boff);
            b_pre[p * 2 + 1] = *reinterpret_cast<const float4*>(b_base + boff + 4);
        }
        #pragma unroll
        for (int p = 0; p < 2; ++p) {
            int off = (b_krow + p * 16) * 272 + b_n8 * 16;
            uint2 lo = f4_to_h4(b_pre[p * 2 + 0]), hi = f4_to_h4(b_pre[p * 2 + 1]);
            *reinterpret_cast<uint4*>(sbuf + 20480 + off) = make_uint4(lo.x, lo.y, hi.x, hi.y);
        }
    }
    CP_WAIT0();
    __syncthreads();

    const int NK = FF / 32;   // 16
    for (int kc = 0; kc < NK; ++kc) {
        const int cur = kc & 1;
        const int has_next = (kc + 1 < NK);
        if (has_next) {
            const int k0 = (kc + 1) * 32;
            const uint32_t Ad = sA + (cur ^ 1) * 10240 + a_row * 80 + a_q4 * 16;
            cp_async16(Ad,           a_base + (size_t)a_row * FF + k0 + a_q4 * 8);
            cp_async16(Ad + 64 * 80, a_base + (size_t)(a_row + 64) * FF + k0 + a_q4 * 8);
            CP_COMMIT();
            #pragma unroll
            for (int p = 0; p < 2; ++p) {
                size_t boff = (size_t)(k0 + b_krow + p * 16) * HH + b_n8 * 8;
                b_pre[p * 2 + 0] = *reinterpret_cast<const float4*>(b_base + boff);
                b_pre[p * 2 + 1] = *reinterpret_cast<const float4*>(b_base + boff + 4);
            }
        }

        const uint32_t Ab = sA + cur * 10240;
        const uint32_t Bb = sA + 20480 + cur * 8704;
        #pragma unroll
        for (int ks = 0; ks < 2; ++ks) {
            uint32_t a[2][4];
            #pragma unroll
            for (int mi = 0; mi < 2; ++mi)
                ldm_x4(a[mi], Ab + (wm * 32 + mi * 16 + fa_row) * 80 + ks * 32 + fa_koff);
            #pragma unroll
            for (int pf = 0; pf < 4; ++pf) {
                uint32_t b[4];
                ldm_x4t(b, Bb + (ks * 16 + fb_k) * 272 + fb_noff + pf * 32);
                #pragma unroll
                for (int mi = 0; mi < 2; ++mi) {
                    mma_f16(acc[mi][pf * 2 + 0], a[mi], b + 0);
                    mma_f16(acc[mi][pf * 2 + 1], a[mi], b + 2);
                }
            }
        }

        if (has_next) {
            unsigned char* nb = sbuf + 20480 + (cur ^ 1) * 8704;
            #pragma unroll
            for (int p = 0; p < 2; ++p) {
                int off = (b_krow + p * 16) * 272 + b_n8 * 16;
                uint2 lo = f4_to_h4(b_pre[p * 2 + 0]), hi = f4_to_h4(b_pre[p * 2 + 1]);
                *reinterpret_cast<uint4*>(nb + off) = make_uint4(lo.x, lo.y, hi.x, hi.y);
            }
        }
        CP_WAIT0();
        __syncthreads();
    }

    const int frow = lane >> 2;
    const int fcol = (lane & 3) * 2;
    #pragma unroll
    for (int mi = 0; mi < 2; ++mi) {
        #pragma unroll
        for (int nj = 0; nj < 8; ++nj) {
            int m = m0 + wm * 32 + mi * 16 + frow;
            int n = n0 + wn * 64 + nj * 8 + fcol;
            #pragma unroll
            for (int half = 0; half < 2; ++half) {
                *reinterpret_cast<__half2*>(
                    &g_obuf[((size_t)e * CC + m + half * 8) * HH + n]) =
                    __floats2half2_rn(acc[mi][nj][half * 2 + 0],
                                      acc[mi][nj][half * 2 + 1]);
            }
        }
    }
}

// ====================================================================
// Kernel 5: combine — y[t] = sum_k w[t,k] * obuf[row(t,k)]
// ====================================================================
__global__ void __launch_bounds__(128) combine_kernel(float* __restrict__ y)
{
    int t = blockIdx.x;
    __shared__ int   srow[KK];
    __shared__ float sw[KK];
    if (threadIdx.x < KK) {
        int i = t * KK + threadIdx.x;
        int e = g_expert_index[i];
        int p = g_pair_pos[i];
        srow[threadIdx.x] = (p < CC) ? (e * CC + p) : -1;
        sw[threadIdx.x]   = g_weights[i];
    }
    __syncthreads();

    const int h0 = threadIdx.x * 8;
    float a[8];
    #pragma unroll
    for (int q = 0; q < 8; ++q) a[q] = 0.f;
    #pragma unroll
    for (int k = 0; k < KK; ++k) {
        int r = srow[k];
        if (r >= 0) {
            float wk = sw[k];
            uint4 v = *reinterpret_cast<const uint4*>(&g_obuf[(size_t)r * HH + h0]);
            const __half2* hp = reinterpret_cast<const __half2*>(&v);
            #pragma unroll
            for (int q = 0; q < 4; ++q) {
                float2 f = __half22float2(hp[q]);
                a[q * 2 + 0] += wk * f.x;
                a[q * 2 + 1] += wk * f.y;
            }
        }
    }
    float4* yp = reinterpret_cast<float4*>(&y[(size_t)t * HH + h0]);
    yp[0] = make_float4(a[0], a[1], a[2], a[3]);
    yp[1] = make_float4(a[4], a[5], a[6], a[7]);
}

// ====================================================================
extern "C" void kernel_launch(void* const* d_in, const int* in_sizes, int n_in,
                              void* d_out, int out_size)
{
    const float* x        = (const float*)d_in[0];
    const float* w_router = (const float*)d_in[1];
    const float* bias     = (const float*)d_in[2];
    const float* w_gate   = (const float*)d_in[3];
    const float* w_up     = (const float*)d_in[4];
    const float* w_down   = (const float*)d_in[5];

    float* y = (float*)d_out;
    float* logits_out = nullptr;
    float* idx_out    = nullptr;
    long long base = (long long)TT * HH;
    if ((long long)out_size >= base + (long long)TT * EE)
        logits_out = y + base;
    if ((long long)out_size >= base + (long long)TT * EE + (long long)TT * KK)
        idx_out = y + base + (long long)TT * EE;

    const int SMEM1 = 49152;
    cudaFuncSetAttribute(gemm1_mma, cudaFuncAttributeMaxDynamicSharedMemorySize, SMEM1);

    router_kernel<<<TT / 16, 256>>>(x, w_router, bias, logits_out, idx_out);
    pos_kernel<<<EE, 256>>>();
    gemm1_mma<<<dim3(CC / 128, FF / 64, EE), 256, SMEM1>>>(w_gate, w_up);
    gemm2_mma<<<dim3(CC / 128, HH / 128, EE), 256>>>(w_down);
    combine_kernel<<<TT, 128>>>(y);
}